// round 10
// baseline (speedup 1.0000x reference)
#include <cuda_runtime.h>
#include <cuda_bf16.h>
#include <math.h>
#include <stdint.h>

#define N_NODES 4096
#define C_COMM  32
#define TOK     (32*4096*16)
#define NTILES  (TOK/16)        // 131072 warp-tiles of 16 tokens
#define GRID_CTAS 296
#define NWARPS  (GRID_CTAS*8)   // 2368

// ---------------- device scratch ----------------
__device__ float  g_G[C_COMM * 64];
__device__ int    g_cls[N_NODES];
__device__ double g_zr[C_COMM*8], g_zi[C_COMM*8], g_cr[C_COMM*8], g_ci[C_COMM*8];
// B-fragment tables: [3 blocks][88 pos][32 lanes] x uint2  (67584 B)
__device__ uint2  g_btab[3 * 88 * 32];

// ---------------- smem float layout ----------------
#define F_BTAB 0          // 16896 floats (btab as raw)
#define F_B0   16896      // 192
#define F_B1   17088      // 192
#define F_B2   17280      // 24
#define F_G    17304      // 2048
#define F_SIN  19352      // 8 warps x 16 x 16
#define F_SD   21400      // 8 warps x 16 x 8
#define SMEM_FLOATS 22424
#define SMEM_TOTAL  (SMEM_FLOATS*4)

#define MMA4(D, A, B0, B1) asm volatile( \
    "mma.sync.aligned.m16n8k16.row.col.f32.bf16.bf16.f32 " \
    "{%0,%1,%2,%3},{%4,%5,%6,%7},{%8,%9},{%0,%1,%2,%3};" \
    : "+f"((D)[0]), "+f"((D)[1]), "+f"((D)[2]), "+f"((D)[3]) \
    : "r"((A)[0]), "r"((A)[1]), "r"((A)[2]), "r"((A)[3]), "r"(B0), "r"(B1))

// split v = hi + lo (hi = truncate-to-bf16, lo = bf16 residual); pack pairs
__device__ __forceinline__ void splitpack(float v0, float v1, uint32_t& hi, uint32_t& lo) {
    uint32_t u0 = __float_as_uint(v0), u1 = __float_as_uint(v1);
    hi = __byte_perm(u0, u1, 0x7632);
    float h0 = __uint_as_float(u0 & 0xFFFF0000u);
    float h1 = __uint_as_float(u1 & 0xFFFF0000u);
    asm("cvt.rn.bf16x2.f32 %0, %1, %2;" : "=r"(lo) : "f"(v1 - h1), "f"(v0 - h0));
}

// ============================================================================
// Kernel 1a: fp32 Hessenberg + Francis QR eigenvalues, fp64 Newton coeffs
// ============================================================================
__global__ void eig_vals_kernel(const float* __restrict__ koop)
{
    int c = blockIdx.x;
    if (threadIdx.x != 0) return;
    float a[8][8];
    for (int i = 0; i < 8; i++)
        for (int j = 0; j < 8; j++)
            a[i][j] = koop[c * 64 + i * 8 + j];
    for (int k = 0; k < 6; k++) {
        float nx = 0.f;
        for (int i = k + 1; i < 8; i++) nx += a[i][k] * a[i][k];
        nx = sqrtf(nx);
        if (nx < 1e-30f) continue;
        float x0 = a[k + 1][k];
        float alpha = (x0 >= 0.f) ? -nx : nx;
        float v[8];
        for (int i = 0; i < 8; i++) v[i] = 0.f;
        v[k + 1] = x0 - alpha;
        for (int i = k + 2; i < 8; i++) v[i] = a[i][k];
        float vv = 0.f;
        for (int i = k + 1; i < 8; i++) vv += v[i] * v[i];
        if (vv < 1e-30f) continue;
        float beta = 2.f / vv;
        for (int j = 0; j < 8; j++) {
            float s = 0.f;
            for (int i = k + 1; i < 8; i++) s += v[i] * a[i][j];
            s *= beta;
            for (int i = k + 1; i < 8; i++) a[i][j] -= v[i] * s;
        }
        for (int i = 0; i < 8; i++) {
            float s = 0.f;
            for (int j = k + 1; j < 8; j++) s += a[i][j] * v[j];
            s *= beta;
            for (int j = k + 1; j < 8; j++) a[i][j] -= s * v[j];
        }
    }
    float wr[8], wi[8];
    float anorm = 0.f;
    for (int i = 0; i < 8; i++) {
        int j0 = (i - 1 > 0) ? (i - 1) : 0;
        for (int j = j0; j < 8; j++) anorm += fabsf(a[i][j]);
    }
    const float EPSF = 1.1920929e-07f;
    int nn = 7; float t = 0.f; int guard = 0;
    while (nn >= 0 && guard < 2000) {
        int its = 0, l = 0;
        do {
            guard++;
            if (guard >= 2000) { wr[nn] = a[nn][nn] + t; wi[nn] = 0.f; nn--; break; }
            for (l = nn; l >= 1; l--) {
                float s = fabsf(a[l - 1][l - 1]) + fabsf(a[l][l]);
                if (s == 0.f) s = anorm;
                if (fabsf(a[l][l - 1]) <= EPSF * s) { a[l][l - 1] = 0.f; break; }
            }
            if (l < 0) l = 0;
            float x = a[nn][nn];
            if (l == nn) { wr[nn] = x + t; wi[nn] = 0.f; nn--; }
            else {
                float y = a[nn - 1][nn - 1];
                float w = a[nn][nn - 1] * a[nn - 1][nn];
                if (l == nn - 1) {
                    float p = 0.5f * (y - x);
                    float q = p * p + w;
                    float z = sqrtf(fabsf(q));
                    x += t;
                    if (q >= 0.f) {
                        z = p + ((p >= 0.f) ? z : -z);
                        wr[nn - 1] = wr[nn] = x + z;
                        if (z != 0.f) wr[nn] = x - w / z;
                        wi[nn - 1] = wi[nn] = 0.f;
                    } else {
                        wr[nn - 1] = wr[nn] = x + p;
                        wi[nn] = z; wi[nn - 1] = -z;
                    }
                    nn -= 2;
                } else {
                    float p = 0.f, q = 0.f, r = 0.f, z, s, u, v;
                    if (its == 10 || its == 20) {
                        t += x;
                        for (int i = 0; i <= nn; i++) a[i][i] -= x;
                        s = fabsf(a[nn][nn - 1]) + fabsf(a[nn - 1][nn - 2]);
                        y = x = 0.75f * s;
                        w = -0.4375f * s * s;
                    }
                    its++;
                    if (its > 50) { wr[nn] = a[nn][nn] + t; wi[nn] = 0.f; nn--; break; }
                    int m;
                    for (m = nn - 2; m >= l; m--) {
                        z = a[m][m]; r = x - z; s = y - z;
                        p = (r * s - w) / a[m + 1][m] + a[m][m + 1];
                        q = a[m + 1][m + 1] - z - r - s;
                        r = a[m + 2][m + 1];
                        s = fabsf(p) + fabsf(q) + fabsf(r);
                        p /= s; q /= s; r /= s;
                        if (m == l) break;
                        u = fabsf(a[m][m - 1]) * (fabsf(q) + fabsf(r));
                        v = fabsf(p) * (fabsf(a[m - 1][m - 1]) + fabsf(z) + fabsf(a[m + 1][m + 1]));
                        if (u <= EPSF * v) break;
                    }
                    for (int i = m + 2; i <= nn; i++) {
                        a[i][i - 2] = 0.f;
                        if (i != m + 2) a[i][i - 3] = 0.f;
                    }
                    for (int k = m; k <= nn - 1; k++) {
                        if (k != m) {
                            p = a[k][k - 1]; q = a[k + 1][k - 1];
                            r = (k != nn - 1) ? a[k + 2][k - 1] : 0.f;
                            x = fabsf(p) + fabsf(q) + fabsf(r);
                            if (x != 0.f) { p /= x; q /= x; r /= x; }
                        }
                        s = sqrtf(p * p + q * q + r * r);
                        if (p < 0.f) s = -s;
                        if (s != 0.f) {
                            if (k == m) { if (l != m) a[k][k - 1] = -a[k][k - 1]; }
                            else a[k][k - 1] = -s * x;
                            p += s; x = p / s; y = q / s; z = r / s; q /= p; r /= p;
                            for (int j = k; j <= nn; j++) {
                                float pp = a[k][j] + q * a[k + 1][j];
                                if (k != nn - 1) { pp += r * a[k + 2][j]; a[k + 2][j] -= pp * z; }
                                a[k + 1][j] -= pp * y;
                                a[k][j]     -= pp * x;
                            }
                            int mmin = (nn < k + 3) ? nn : (k + 3);
                            for (int i = l; i <= mmin; i++) {
                                float pp = x * a[i][k] + y * a[i][k + 1];
                                if (k != nn - 1) { pp += z * a[i][k + 2]; a[i][k + 2] -= pp * r; }
                                a[i][k + 1] -= pp * q;
                                a[i][k]     -= pp;
                            }
                        }
                    }
                }
            }
        } while (l < nn - 1);
    }
    double zr[8], zi[8];
    for (int i = 0; i < 8; i++) { zr[i] = (double)wr[i] + 1e-10; zi[i] = (double)wi[i] + 1e-10; }
    bool mask[8]; bool any = false;
    for (int i = 0; i < 8; i++) {
        double am = sqrt(zr[i] * zr[i] + zi[i] * zi[i]);
        mask[i] = (am <= 1.1 && am >= 0.9);
        any = any || mask[i];
    }
    if (!any) for (int i = 0; i < 8; i++) mask[i] = true;
    for (int i = 1; i < 8; i++)
        for (int j = 0; j < i; j++)
            if (fabs(zr[i] - zr[j]) < 1e-9 && fabs(zi[i] - zi[j]) < 1e-9) {
                zr[i] += 1.0e-8 * (i + 1);
                zi[i] += 0.7e-8 * (i + 1);
            }
    double cr[8], ci[8];
    for (int i = 0; i < 8; i++) {
        cr[i] = mask[i] ? zr[i] : 0.0;
        ci[i] = mask[i] ? zi[i] : 0.0;
    }
    for (int j = 1; j < 8; j++)
        for (int i = 7; i >= j; i--) {
            double nr = cr[i] - cr[i - 1], ni = ci[i] - ci[i - 1];
            double dr = zr[i] - zr[i - j], di = zi[i] - zi[i - j];
            double d2 = dr * dr + di * di;
            cr[i] = (nr * dr + ni * di) / d2;
            ci[i] = (ni * dr - nr * di) / d2;
        }
    for (int i = 0; i < 8; i++) {
        g_zr[c * 8 + i] = zr[i]; g_zi[c * 8 + i] = zi[i];
        g_cr[c * 8 + i] = cr[i]; g_ci[c * 8 + i] = ci[i];
    }
}

// ============================================================================
// Kernel 1b: parallel complex Horner p(A) -> G (64 threads per matrix, fp64)
// ============================================================================
__global__ void horner_kernel(const float* __restrict__ koop)
{
    int c = blockIdx.x;
    int t = threadIdx.x;
    int i = t >> 3, j = t & 7;
    __shared__ double sA[64], sMr[64], sMi[64], szr[8], szi[8], scr[8], sci[8];
    sA[t] = (double)koop[c * 64 + t];
    if (t < 8) {
        szr[t] = g_zr[c * 8 + t]; szi[t] = g_zi[c * 8 + t];
        scr[t] = g_cr[c * 8 + t]; sci[t] = g_ci[c * 8 + t];
    }
    __syncthreads();
    double mr = (i == j) ? scr[7] : 0.0;
    double mi = (i == j) ? sci[7] : 0.0;
    sMr[t] = mr; sMi[t] = mi;
    __syncthreads();
    for (int k = 6; k >= 0; k--) {
        double tr = 0.0, ti = 0.0;
#pragma unroll
        for (int q = 0; q < 8; q++) {
            tr += sA[i * 8 + q] * sMr[q * 8 + j];
            ti += sA[i * 8 + q] * sMi[q * 8 + j];
        }
        double omr = mr, omi = mi;
        __syncthreads();
        mr = tr - (szr[k] * omr - szi[k] * omi) + ((i == j) ? scr[k] : 0.0);
        mi = ti - (szr[k] * omi + szi[k] * omr) + ((i == j) ? sci[k] : 0.0);
        sMr[t] = mr; sMi[t] = mi;
        __syncthreads();
    }
    g_G[c * 64 + t] = (float)mr;
}

// ============================================================================
// Kernel 2: community argmax
// ============================================================================
__global__ void argmax_kernel(const float* __restrict__ comm)
{
    int n = blockIdx.x * blockDim.x + threadIdx.x;
    if (n >= N_NODES) return;
    float best = comm[n * C_COMM];
    int bi = 0;
#pragma unroll
    for (int cc = 1; cc < C_COMM; cc++) {
        float v = comm[n * C_COMM + cc];
        if (v > best) { best = v; bi = cc; }
    }
    g_cls[n] = bi;
}

// ============================================================================
// Kernel 3: build per-lane B-fragment tables (hi/lo bf16, m16n8k16 layout).
// grid = (3 blocks, 11 slabs).
// ============================================================================
__global__ void wprep_kernel(const float* __restrict__ W0,
                             const float* __restrict__ W1,
                             const float* __restrict__ W2)
{
    int blk = blockIdx.x;
    int idx = blockIdx.y * 256 + threadIdx.x;
    if (idx >= 88 * 32) return;
    {
        int pos = idx >> 5, lane = idx & 31;
        int v, jn, kb, layer;
        if (pos < 16)      { layer = 0; v = pos & 1; jn = pos >> 1; kb = 0; }
        else if (pos < 80) { int p = pos - 16; v = p & 1; int q = p >> 1; kb = q & 3; jn = q >> 2; layer = 1; }
        else               { int p = pos - 80; v = p & 1; kb = p >> 1; jn = 0; layer = 2; }
        int n = jn * 8 + (lane >> 2);
        int k0 = 16 * kb + 2 * (lane & 3);
        float w[4];
#pragma unroll
        for (int e = 0; e < 4; e++) {
            int k = k0 + (e >> 1) * 8 + (e & 1);
            float val = 0.f;
            if (layer == 0)      { if (k < 12) val = W0[blk * 768 + k * 64 + n]; }
            else if (layer == 1) { val = W1[blk * 4096 + k * 64 + n]; }
            else                 { val = W2[blk * 512 + k * 8 + n]; }
            __nv_bfloat16 bh = __float2bfloat16(val);
            if (v == 0) w[e] = __bfloat162float(bh);
            else        w[e] = __bfloat162float(__float2bfloat16(val - __bfloat162float(bh)));
        }
        uint32_t px = ((uint32_t)__bfloat16_as_ushort(__float2bfloat16(w[1])) << 16)
                    |  (uint32_t)__bfloat16_as_ushort(__float2bfloat16(w[0]));
        uint32_t py = ((uint32_t)__bfloat16_as_ushort(__float2bfloat16(w[3])) << 16)
                    |  (uint32_t)__bfloat16_as_ushort(__float2bfloat16(w[2]));
        g_btab[(blk * 88 + pos) * 32 + lane] = make_uint2(px, py);
    }
}

// ============================================================================
// Kernel 4: main fused flow via mma.sync bf16x3. Persistent, warp = 16 tokens.
// R10: split accumulators (hihi / hilo / lohi) to break HMMA RAW chains.
// ============================================================================
__global__ void __launch_bounds__(256, 2) main_kernel(
    const float* __restrict__ latent,
    const float* __restrict__ b0g, const float* __restrict__ b1g,
    const float* __restrict__ b2g, float* __restrict__ out)
{
    extern __shared__ float sm[];
    {
        const uint4* src = reinterpret_cast<const uint4*>(g_btab);
        uint4* dst = reinterpret_cast<uint4*>(sm);
        for (int i = threadIdx.x; i < 16896 / 4; i += 256) dst[i] = src[i];
        for (int i = threadIdx.x; i < 192;  i += 256) sm[F_B0 + i] = b0g[i];
        for (int i = threadIdx.x; i < 192;  i += 256) sm[F_B1 + i] = b1g[i];
        for (int i = threadIdx.x; i < 24;   i += 256) sm[F_B2 + i] = b2g[i];
        for (int i = threadIdx.x; i < 2048; i += 256) sm[F_G + i] = g_G[i];
    }
    __syncthreads();

    const int wid = threadIdx.x >> 5;
    const int lane = threadIdx.x & 31;
    const int r = lane >> 2, qq = lane & 3;
    float* stg = sm + F_SIN + wid * 256;
    float* sD  = sm + F_SD  + wid * 128;
    const uint2* btab = reinterpret_cast<const uint2*>(sm);
    const int warpGlobal = blockIdx.x * 8 + wid;

    for (int tile = warpGlobal; tile < NTILES; tile += NWARPS) {
        const int token = tile * 16 + lane;
        float x[8], cond[8];
        if (lane < 16) {
            const float4* lat4 = reinterpret_cast<const float4*>(latent);
            float4 p0 = lat4[token * 2], p1 = lat4[token * 2 + 1];
            x[0] = p0.x; x[1] = p0.y; x[2] = p0.z; x[3] = p0.w;
            x[4] = p1.x; x[5] = p1.y; x[6] = p1.z; x[7] = p1.w;
            const int cls = g_cls[(token >> 4) & (N_NODES - 1)];
            const float* sG = sm + F_G + cls * 64;
#pragma unroll
            for (int e = 0; e < 8; e++) cond[e] = 0.f;
#pragma unroll
            for (int d = 0; d < 8; d++) {
                float xd = x[d];
#pragma unroll
                for (int e = 0; e < 8; e++) cond[e] = fmaf(xd, sG[d * 8 + e], cond[e]);
            }
        }
        float logdet = 0.f;

#pragma unroll 1
        for (int blk = 0; blk < 3; blk++) {
            const int off1 = (blk & 1) ? 4 : 0;
            const int off2 = 4 - off1;
            const int tb0 = blk * 88;

            if (lane < 16) {
#pragma unroll
                for (int q = 0; q < 4; q++) stg[lane * 16 + q] = x[off1 + q];
#pragma unroll
                for (int q = 0; q < 8; q++) stg[lane * 16 + 4 + q] = cond[q];
            }
            __syncwarp();

            uint32_t Ah[4], Al[4];
            {
                float2 p00 = *reinterpret_cast<float2*>(stg + r * 16 + qq * 2);
                float2 p10 = *reinterpret_cast<float2*>(stg + (r + 8) * 16 + qq * 2);
                float2 p08 = make_float2(0.f, 0.f), p18 = p08;
                if (qq < 2) {
                    p08 = *reinterpret_cast<float2*>(stg + r * 16 + qq * 2 + 8);
                    p18 = *reinterpret_cast<float2*>(stg + (r + 8) * 16 + qq * 2 + 8);
                }
                splitpack(p00.x, p00.y, Ah[0], Al[0]);
                splitpack(p10.x, p10.y, Ah[1], Al[1]);
                splitpack(p08.x, p08.y, Ah[2], Al[2]);
                splitpack(p18.x, p18.y, Ah[3], Al[3]);
            }
            __syncwarp();

            // ---- layer 0: 12(->16) -> 64, split accumulators ----
            uint32_t A1h[16], A1l[16];
#pragma unroll
            for (int jn = 0; jn < 8; jn++) {
                float2 bia = *reinterpret_cast<const float2*>(sm + F_B0 + blk * 64 + jn * 8 + qq * 2);
                float D1[4] = { bia.x, bia.y, bia.x, bia.y };
                float D2[4] = { 0.f, 0.f, 0.f, 0.f };
                float D3[4] = { 0.f, 0.f, 0.f, 0.f };
                const uint2* tb = btab + (tb0 + jn * 2) * 32 + lane;
                uint2 bh = tb[0], bl = tb[32];
                MMA4(D1, Ah, bh.x, bh.y);
                MMA4(D2, Ah, bl.x, bl.y);
                MMA4(D3, Al, bh.x, bh.y);
                float h0 = fmaxf(D1[0] + D2[0] + D3[0], 0.f);
                float h1 = fmaxf(D1[1] + D2[1] + D3[1], 0.f);
                float h2 = fmaxf(D1[2] + D2[2] + D3[2], 0.f);
                float h3 = fmaxf(D1[3] + D2[3] + D3[3], 0.f);
                splitpack(h0, h1, A1h[jn * 2],     A1l[jn * 2]);
                splitpack(h2, h3, A1h[jn * 2 + 1], A1l[jn * 2 + 1]);
            }

            // ---- layer 1: 64 -> 64, split accumulators ----
            uint32_t A2h[16], A2l[16];
#pragma unroll
            for (int jn = 0; jn < 8; jn++) {
                float2 bia = *reinterpret_cast<const float2*>(sm + F_B1 + blk * 64 + jn * 8 + qq * 2);
                float D1[4] = { bia.x, bia.y, bia.x, bia.y };
                float D2[4] = { 0.f, 0.f, 0.f, 0.f };
                float D3[4] = { 0.f, 0.f, 0.f, 0.f };
#pragma unroll
                for (int kb = 0; kb < 4; kb++) {
                    const uint2* tb = btab + (tb0 + 16 + (jn * 4 + kb) * 2) * 32 + lane;
                    uint2 bh = tb[0], bl = tb[32];
                    MMA4(D1, (A1h + 4 * kb), bh.x, bh.y);
                    MMA4(D2, (A1h + 4 * kb), bl.x, bl.y);
                    MMA4(D3, (A1l + 4 * kb), bh.x, bh.y);
                }
                float h0 = fmaxf(D1[0] + D2[0] + D3[0], 0.f);
                float h1 = fmaxf(D1[1] + D2[1] + D3[1], 0.f);
                float h2 = fmaxf(D1[2] + D2[2] + D3[2], 0.f);
                float h3 = fmaxf(D1[3] + D2[3] + D3[3], 0.f);
                splitpack(h0, h1, A2h[jn * 2],     A2l[jn * 2]);
                splitpack(h2, h3, A2h[jn * 2 + 1], A2l[jn * 2 + 1]);
            }

            // ---- layer 2: 64 -> 8, split accumulators ----
            {
                float2 bia = *reinterpret_cast<const float2*>(sm + F_B2 + blk * 8 + qq * 2);
                float D1[4] = { bia.x, bia.y, bia.x, bia.y };
                float D2[4] = { 0.f, 0.f, 0.f, 0.f };
                float D3[4] = { 0.f, 0.f, 0.f, 0.f };
#pragma unroll
                for (int kb = 0; kb < 4; kb++) {
                    const uint2* tb = btab + (tb0 + 80 + kb * 2) * 32 + lane;
                    uint2 bh = tb[0], bl = tb[32];
                    MMA4(D1, (A2h + 4 * kb), bh.x, bh.y);
                    MMA4(D2, (A2h + 4 * kb), bl.x, bl.y);
                    MMA4(D3, (A2l + 4 * kb), bh.x, bh.y);
                }
                sD[r * 8 + qq * 2]           = D1[0] + D2[0] + D3[0];
                sD[r * 8 + qq * 2 + 1]       = D1[1] + D2[1] + D3[1];
                sD[(r + 8) * 8 + qq * 2]     = D1[2] + D2[2] + D3[2];
                sD[(r + 8) * 8 + qq * 2 + 1] = D1[3] + D2[3] + D3[3];
            }
            __syncwarp();

            if (lane < 16) {
                float4 oa = *reinterpret_cast<float4*>(sD + lane * 8);
                float4 ob = *reinterpret_cast<float4*>(sD + lane * 8 + 4);
                float s0 = tanhf(oa.x), s1 = tanhf(oa.y), s2 = tanhf(oa.z), s3 = tanhf(oa.w);
                logdet += s0 + s1 + s2 + s3;
                x[off2 + 0] = x[off2 + 0] * expf(s0) + ob.x;
                x[off2 + 1] = x[off2 + 1] * expf(s1) + ob.y;
                x[off2 + 2] = x[off2 + 2] * expf(s2) + ob.z;
                x[off2 + 3] = x[off2 + 3] * expf(s3) + ob.w;
            }
            __syncwarp();
        }

        if (lane < 16) {
            float ss = 0.f;
#pragma unroll
            for (int q = 0; q < 8; q++) ss += x[q] * x[q];
            out[token] = -0.5f * ss - 7.3515082656f + logdet;
        }
    }
}

// ============================================================================
extern "C" void kernel_launch(void* const* d_in, const int* in_sizes, int n_in,
                              void* d_out, int out_size)
{
    const float* latent = (const float*)d_in[0];
    const float* koop   = (const float*)d_in[1];
    const float* comm   = (const float*)d_in[2];
    const float* W0     = (const float*)d_in[3];
    const float* b0     = (const float*)d_in[4];
    const float* W1     = (const float*)d_in[5];
    const float* b1     = (const float*)d_in[6];
    const float* W2     = (const float*)d_in[7];
    const float* b2     = (const float*)d_in[8];
    float* out = (float*)d_out;

    eig_vals_kernel<<<C_COMM, 1>>>(koop);
    horner_kernel<<<C_COMM, 64>>>(koop);
    argmax_kernel<<<N_NODES / 256, 256>>>(comm);
    wprep_kernel<<<dim3(3, 11), 256>>>(W0, W1, W2);

    (void)cudaFuncSetAttribute(main_kernel,
                               cudaFuncAttributeMaxDynamicSharedMemorySize, SMEM_TOTAL);
    main_kernel<<<GRID_CTAS, 256, SMEM_TOTAL>>>(latent, b0, b1, b2, out);
}

// round 11
// speedup vs baseline: 1.0705x; 1.0705x over previous
#include <cuda_runtime.h>
#include <cuda_bf16.h>
#include <math.h>
#include <stdint.h>

#define N_NODES 4096
#define C_COMM  32
#define TOK     (32*4096*16)
#define NTILES  (TOK/16)        // 131072 warp-tiles of 16 tokens
#define GRID_CTAS 296
#define NWARPS  (GRID_CTAS*8)   // 2368

// ---------------- device scratch ----------------
__device__ float  g_G[C_COMM * 64];
__device__ int    g_cls[N_NODES];
__device__ double g_zr[C_COMM*8], g_zi[C_COMM*8], g_cr[C_COMM*8], g_ci[C_COMM*8];
// B-fragment tables: [3 blocks][88 pos][32 lanes] x uint2  (67584 B)
__device__ uint2  g_btab[3 * 88 * 32];

// ---------------- smem float layout ----------------
#define F_BTAB 0          // 16896 floats (btab as raw)
#define F_B0   16896      // 192
#define F_B1   17088      // 192
#define F_B2   17280      // 24
#define F_G    17304      // 2048
#define F_SIN  19352      // 8 warps x 16 x 16
#define F_SD   21400      // 8 warps x 16 x 8
#define SMEM_FLOATS 22424
#define SMEM_TOTAL  (SMEM_FLOATS*4)

#define MMA4(D, A, B0, B1) asm volatile( \
    "mma.sync.aligned.m16n8k16.row.col.f32.bf16.bf16.f32 " \
    "{%0,%1,%2,%3},{%4,%5,%6,%7},{%8,%9},{%0,%1,%2,%3};" \
    : "+f"((D)[0]), "+f"((D)[1]), "+f"((D)[2]), "+f"((D)[3]) \
    : "r"((A)[0]), "r"((A)[1]), "r"((A)[2]), "r"((A)[3]), "r"(B0), "r"(B1))

// split v = hi + lo (hi = truncate-to-bf16, lo = bf16 residual); pack pairs
__device__ __forceinline__ void splitpack(float v0, float v1, uint32_t& hi, uint32_t& lo) {
    uint32_t u0 = __float_as_uint(v0), u1 = __float_as_uint(v1);
    hi = __byte_perm(u0, u1, 0x7632);
    float h0 = __uint_as_float(u0 & 0xFFFF0000u);
    float h1 = __uint_as_float(u1 & 0xFFFF0000u);
    asm("cvt.rn.bf16x2.f32 %0, %1, %2;" : "=r"(lo) : "f"(v1 - h1), "f"(v0 - h0));
}

// fast transcendentals (MUFU-based); s-range here is tiny so error ~1e-7
__device__ __forceinline__ float fast_tanh(float x) {
    float e = __expf(2.f * x);               // inf for large x, 0 for very neg
    return 1.f - __fdividef(2.f, e + 1.f);   // saturates correctly at +/-1
}

// ============================================================================
// Kernel 1a: fp32 Hessenberg + Francis QR eigenvalues, fp64 Newton coeffs
// ============================================================================
__global__ void eig_vals_kernel(const float* __restrict__ koop)
{
    int c = blockIdx.x;
    if (threadIdx.x != 0) return;
    float a[8][8];
    for (int i = 0; i < 8; i++)
        for (int j = 0; j < 8; j++)
            a[i][j] = koop[c * 64 + i * 8 + j];
    for (int k = 0; k < 6; k++) {
        float nx = 0.f;
        for (int i = k + 1; i < 8; i++) nx += a[i][k] * a[i][k];
        nx = sqrtf(nx);
        if (nx < 1e-30f) continue;
        float x0 = a[k + 1][k];
        float alpha = (x0 >= 0.f) ? -nx : nx;
        float v[8];
        for (int i = 0; i < 8; i++) v[i] = 0.f;
        v[k + 1] = x0 - alpha;
        for (int i = k + 2; i < 8; i++) v[i] = a[i][k];
        float vv = 0.f;
        for (int i = k + 1; i < 8; i++) vv += v[i] * v[i];
        if (vv < 1e-30f) continue;
        float beta = 2.f / vv;
        for (int j = 0; j < 8; j++) {
            float s = 0.f;
            for (int i = k + 1; i < 8; i++) s += v[i] * a[i][j];
            s *= beta;
            for (int i = k + 1; i < 8; i++) a[i][j] -= v[i] * s;
        }
        for (int i = 0; i < 8; i++) {
            float s = 0.f;
            for (int j = k + 1; j < 8; j++) s += a[i][j] * v[j];
            s *= beta;
            for (int j = k + 1; j < 8; j++) a[i][j] -= s * v[j];
        }
    }
    float wr[8], wi[8];
    float anorm = 0.f;
    for (int i = 0; i < 8; i++) {
        int j0 = (i - 1 > 0) ? (i - 1) : 0;
        for (int j = j0; j < 8; j++) anorm += fabsf(a[i][j]);
    }
    const float EPSF = 1.1920929e-07f;
    int nn = 7; float t = 0.f; int guard = 0;
    while (nn >= 0 && guard < 2000) {
        int its = 0, l = 0;
        do {
            guard++;
            if (guard >= 2000) { wr[nn] = a[nn][nn] + t; wi[nn] = 0.f; nn--; break; }
            for (l = nn; l >= 1; l--) {
                float s = fabsf(a[l - 1][l - 1]) + fabsf(a[l][l]);
                if (s == 0.f) s = anorm;
                if (fabsf(a[l][l - 1]) <= EPSF * s) { a[l][l - 1] = 0.f; break; }
            }
            if (l < 0) l = 0;
            float x = a[nn][nn];
            if (l == nn) { wr[nn] = x + t; wi[nn] = 0.f; nn--; }
            else {
                float y = a[nn - 1][nn - 1];
                float w = a[nn][nn - 1] * a[nn - 1][nn];
                if (l == nn - 1) {
                    float p = 0.5f * (y - x);
                    float q = p * p + w;
                    float z = sqrtf(fabsf(q));
                    x += t;
                    if (q >= 0.f) {
                        z = p + ((p >= 0.f) ? z : -z);
                        wr[nn - 1] = wr[nn] = x + z;
                        if (z != 0.f) wr[nn] = x - w / z;
                        wi[nn - 1] = wi[nn] = 0.f;
                    } else {
                        wr[nn - 1] = wr[nn] = x + p;
                        wi[nn] = z; wi[nn - 1] = -z;
                    }
                    nn -= 2;
                } else {
                    float p = 0.f, q = 0.f, r = 0.f, z, s, u, v;
                    if (its == 10 || its == 20) {
                        t += x;
                        for (int i = 0; i <= nn; i++) a[i][i] -= x;
                        s = fabsf(a[nn][nn - 1]) + fabsf(a[nn - 1][nn - 2]);
                        y = x = 0.75f * s;
                        w = -0.4375f * s * s;
                    }
                    its++;
                    if (its > 50) { wr[nn] = a[nn][nn] + t; wi[nn] = 0.f; nn--; break; }
                    int m;
                    for (m = nn - 2; m >= l; m--) {
                        z = a[m][m]; r = x - z; s = y - z;
                        p = (r * s - w) / a[m + 1][m] + a[m][m + 1];
                        q = a[m + 1][m + 1] - z - r - s;
                        r = a[m + 2][m + 1];
                        s = fabsf(p) + fabsf(q) + fabsf(r);
                        p /= s; q /= s; r /= s;
                        if (m == l) break;
                        u = fabsf(a[m][m - 1]) * (fabsf(q) + fabsf(r));
                        v = fabsf(p) * (fabsf(a[m - 1][m - 1]) + fabsf(z) + fabsf(a[m + 1][m + 1]));
                        if (u <= EPSF * v) break;
                    }
                    for (int i = m + 2; i <= nn; i++) {
                        a[i][i - 2] = 0.f;
                        if (i != m + 2) a[i][i - 3] = 0.f;
                    }
                    for (int k = m; k <= nn - 1; k++) {
                        if (k != m) {
                            p = a[k][k - 1]; q = a[k + 1][k - 1];
                            r = (k != nn - 1) ? a[k + 2][k - 1] : 0.f;
                            x = fabsf(p) + fabsf(q) + fabsf(r);
                            if (x != 0.f) { p /= x; q /= x; r /= x; }
                        }
                        s = sqrtf(p * p + q * q + r * r);
                        if (p < 0.f) s = -s;
                        if (s != 0.f) {
                            if (k == m) { if (l != m) a[k][k - 1] = -a[k][k - 1]; }
                            else a[k][k - 1] = -s * x;
                            p += s; x = p / s; y = q / s; z = r / s; q /= p; r /= p;
                            for (int j = k; j <= nn; j++) {
                                float pp = a[k][j] + q * a[k + 1][j];
                                if (k != nn - 1) { pp += r * a[k + 2][j]; a[k + 2][j] -= pp * z; }
                                a[k + 1][j] -= pp * y;
                                a[k][j]     -= pp * x;
                            }
                            int mmin = (nn < k + 3) ? nn : (k + 3);
                            for (int i = l; i <= mmin; i++) {
                                float pp = x * a[i][k] + y * a[i][k + 1];
                                if (k != nn - 1) { pp += z * a[i][k + 2]; a[i][k + 2] -= pp * r; }
                                a[i][k + 1] -= pp * q;
                                a[i][k]     -= pp;
                            }
                        }
                    }
                }
            }
        } while (l < nn - 1);
    }
    double zr[8], zi[8];
    for (int i = 0; i < 8; i++) { zr[i] = (double)wr[i] + 1e-10; zi[i] = (double)wi[i] + 1e-10; }
    bool mask[8]; bool any = false;
    for (int i = 0; i < 8; i++) {
        double am = sqrt(zr[i] * zr[i] + zi[i] * zi[i]);
        mask[i] = (am <= 1.1 && am >= 0.9);
        any = any || mask[i];
    }
    if (!any) for (int i = 0; i < 8; i++) mask[i] = true;
    for (int i = 1; i < 8; i++)
        for (int j = 0; j < i; j++)
            if (fabs(zr[i] - zr[j]) < 1e-9 && fabs(zi[i] - zi[j]) < 1e-9) {
                zr[i] += 1.0e-8 * (i + 1);
                zi[i] += 0.7e-8 * (i + 1);
            }
    double cr[8], ci[8];
    for (int i = 0; i < 8; i++) {
        cr[i] = mask[i] ? zr[i] : 0.0;
        ci[i] = mask[i] ? zi[i] : 0.0;
    }
    for (int j = 1; j < 8; j++)
        for (int i = 7; i >= j; i--) {
            double nr = cr[i] - cr[i - 1], ni = ci[i] - ci[i - 1];
            double dr = zr[i] - zr[i - j], di = zi[i] - zi[i - j];
            double d2 = dr * dr + di * di;
            cr[i] = (nr * dr + ni * di) / d2;
            ci[i] = (ni * dr - nr * di) / d2;
        }
    for (int i = 0; i < 8; i++) {
        g_zr[c * 8 + i] = zr[i]; g_zi[c * 8 + i] = zi[i];
        g_cr[c * 8 + i] = cr[i]; g_ci[c * 8 + i] = ci[i];
    }
}

// ============================================================================
// Kernel 1b: parallel complex Horner p(A) -> G (64 threads per matrix, fp64)
// ============================================================================
__global__ void horner_kernel(const float* __restrict__ koop)
{
    int c = blockIdx.x;
    int t = threadIdx.x;
    int i = t >> 3, j = t & 7;
    __shared__ double sA[64], sMr[64], sMi[64], szr[8], szi[8], scr[8], sci[8];
    sA[t] = (double)koop[c * 64 + t];
    if (t < 8) {
        szr[t] = g_zr[c * 8 + t]; szi[t] = g_zi[c * 8 + t];
        scr[t] = g_cr[c * 8 + t]; sci[t] = g_ci[c * 8 + t];
    }
    __syncthreads();
    double mr = (i == j) ? scr[7] : 0.0;
    double mi = (i == j) ? sci[7] : 0.0;
    sMr[t] = mr; sMi[t] = mi;
    __syncthreads();
    for (int k = 6; k >= 0; k--) {
        double tr = 0.0, ti = 0.0;
#pragma unroll
        for (int q = 0; q < 8; q++) {
            tr += sA[i * 8 + q] * sMr[q * 8 + j];
            ti += sA[i * 8 + q] * sMi[q * 8 + j];
        }
        double omr = mr, omi = mi;
        __syncthreads();
        mr = tr - (szr[k] * omr - szi[k] * omi) + ((i == j) ? scr[k] : 0.0);
        mi = ti - (szr[k] * omi + szi[k] * omr) + ((i == j) ? sci[k] : 0.0);
        sMr[t] = mr; sMi[t] = mi;
        __syncthreads();
    }
    g_G[c * 64 + t] = (float)mr;
}

// ============================================================================
// Kernel 2: community argmax
// ============================================================================
__global__ void argmax_kernel(const float* __restrict__ comm)
{
    int n = blockIdx.x * blockDim.x + threadIdx.x;
    if (n >= N_NODES) return;
    float best = comm[n * C_COMM];
    int bi = 0;
#pragma unroll
    for (int cc = 1; cc < C_COMM; cc++) {
        float v = comm[n * C_COMM + cc];
        if (v > best) { best = v; bi = cc; }
    }
    g_cls[n] = bi;
}

// ============================================================================
// Kernel 3: build per-lane B-fragment tables (hi/lo bf16, m16n8k16 layout).
// grid = (3 blocks, 11 slabs).
// ============================================================================
__global__ void wprep_kernel(const float* __restrict__ W0,
                             const float* __restrict__ W1,
                             const float* __restrict__ W2)
{
    int blk = blockIdx.x;
    int idx = blockIdx.y * 256 + threadIdx.x;
    if (idx >= 88 * 32) return;
    {
        int pos = idx >> 5, lane = idx & 31;
        int v, jn, kb, layer;
        if (pos < 16)      { layer = 0; v = pos & 1; jn = pos >> 1; kb = 0; }
        else if (pos < 80) { int p = pos - 16; v = p & 1; int q = p >> 1; kb = q & 3; jn = q >> 2; layer = 1; }
        else               { int p = pos - 80; v = p & 1; kb = p >> 1; jn = 0; layer = 2; }
        int n = jn * 8 + (lane >> 2);
        int k0 = 16 * kb + 2 * (lane & 3);
        float w[4];
#pragma unroll
        for (int e = 0; e < 4; e++) {
            int k = k0 + (e >> 1) * 8 + (e & 1);
            float val = 0.f;
            if (layer == 0)      { if (k < 12) val = W0[blk * 768 + k * 64 + n]; }
            else if (layer == 1) { val = W1[blk * 4096 + k * 64 + n]; }
            else                 { val = W2[blk * 512 + k * 8 + n]; }
            __nv_bfloat16 bh = __float2bfloat16(val);
            if (v == 0) w[e] = __bfloat162float(bh);
            else        w[e] = __bfloat162float(__float2bfloat16(val - __bfloat162float(bh)));
        }
        uint32_t px = ((uint32_t)__bfloat16_as_ushort(__float2bfloat16(w[1])) << 16)
                    |  (uint32_t)__bfloat16_as_ushort(__float2bfloat16(w[0]));
        uint32_t py = ((uint32_t)__bfloat16_as_ushort(__float2bfloat16(w[3])) << 16)
                    |  (uint32_t)__bfloat16_as_ushort(__float2bfloat16(w[2]));
        g_btab[(blk * 88 + pos) * 32 + lane] = make_uint2(px, py);
    }
}

// ============================================================================
// Kernel 4: main fused flow via mma.sync bf16x3. Persistent, warp = 16 tokens.
// R11: R9 chained accumulators (reverted R10) + fast MUFU transcendentals.
// ============================================================================
__global__ void __launch_bounds__(256, 2) main_kernel(
    const float* __restrict__ latent,
    const float* __restrict__ b0g, const float* __restrict__ b1g,
    const float* __restrict__ b2g, float* __restrict__ out)
{
    extern __shared__ float sm[];
    {
        const uint4* src = reinterpret_cast<const uint4*>(g_btab);
        uint4* dst = reinterpret_cast<uint4*>(sm);
        for (int i = threadIdx.x; i < 16896 / 4; i += 256) dst[i] = src[i];
        for (int i = threadIdx.x; i < 192;  i += 256) sm[F_B0 + i] = b0g[i];
        for (int i = threadIdx.x; i < 192;  i += 256) sm[F_B1 + i] = b1g[i];
        for (int i = threadIdx.x; i < 24;   i += 256) sm[F_B2 + i] = b2g[i];
        for (int i = threadIdx.x; i < 2048; i += 256) sm[F_G + i] = g_G[i];
    }
    __syncthreads();

    const int wid = threadIdx.x >> 5;
    const int lane = threadIdx.x & 31;
    const int r = lane >> 2, qq = lane & 3;
    float* stg = sm + F_SIN + wid * 256;
    float* sD  = sm + F_SD  + wid * 128;
    const uint2* btab = reinterpret_cast<const uint2*>(sm);
    const int warpGlobal = blockIdx.x * 8 + wid;

    for (int tile = warpGlobal; tile < NTILES; tile += NWARPS) {
        const int token = tile * 16 + lane;
        float x[8], cond[8];
        if (lane < 16) {
            const float4* lat4 = reinterpret_cast<const float4*>(latent);
            float4 p0 = lat4[token * 2], p1 = lat4[token * 2 + 1];
            x[0] = p0.x; x[1] = p0.y; x[2] = p0.z; x[3] = p0.w;
            x[4] = p1.x; x[5] = p1.y; x[6] = p1.z; x[7] = p1.w;
            const int cls = g_cls[(token >> 4) & (N_NODES - 1)];
            const float* sG = sm + F_G + cls * 64;
#pragma unroll
            for (int e = 0; e < 8; e++) cond[e] = 0.f;
#pragma unroll
            for (int d = 0; d < 8; d++) {
                float xd = x[d];
#pragma unroll
                for (int e = 0; e < 8; e++) cond[e] = fmaf(xd, sG[d * 8 + e], cond[e]);
            }
        }
        float logdet = 0.f;

#pragma unroll 1
        for (int blk = 0; blk < 3; blk++) {
            const int off1 = (blk & 1) ? 4 : 0;
            const int off2 = 4 - off1;
            const int tb0 = blk * 88;

            if (lane < 16) {
#pragma unroll
                for (int q = 0; q < 4; q++) stg[lane * 16 + q] = x[off1 + q];
#pragma unroll
                for (int q = 0; q < 8; q++) stg[lane * 16 + 4 + q] = cond[q];
            }
            __syncwarp();

            uint32_t Ah[4], Al[4];
            {
                float2 p00 = *reinterpret_cast<float2*>(stg + r * 16 + qq * 2);
                float2 p10 = *reinterpret_cast<float2*>(stg + (r + 8) * 16 + qq * 2);
                float2 p08 = make_float2(0.f, 0.f), p18 = p08;
                if (qq < 2) {
                    p08 = *reinterpret_cast<float2*>(stg + r * 16 + qq * 2 + 8);
                    p18 = *reinterpret_cast<float2*>(stg + (r + 8) * 16 + qq * 2 + 8);
                }
                splitpack(p00.x, p00.y, Ah[0], Al[0]);
                splitpack(p10.x, p10.y, Ah[1], Al[1]);
                splitpack(p08.x, p08.y, Ah[2], Al[2]);
                splitpack(p18.x, p18.y, Ah[3], Al[3]);
            }
            __syncwarp();

            // ---- layer 0: 12(->16) -> 64 ----
            uint32_t A1h[16], A1l[16];
#pragma unroll
            for (int jn = 0; jn < 8; jn++) {
                float2 bia = *reinterpret_cast<const float2*>(sm + F_B0 + blk * 64 + jn * 8 + qq * 2);
                float D[4] = { bia.x, bia.y, bia.x, bia.y };
                const uint2* tb = btab + (tb0 + jn * 2) * 32 + lane;
                uint2 bh = tb[0], bl = tb[32];
                MMA4(D, Ah, bh.x, bh.y);
                MMA4(D, Ah, bl.x, bl.y);
                MMA4(D, Al, bh.x, bh.y);
                float h0 = fmaxf(D[0], 0.f), h1 = fmaxf(D[1], 0.f);
                float h2 = fmaxf(D[2], 0.f), h3 = fmaxf(D[3], 0.f);
                splitpack(h0, h1, A1h[jn * 2],     A1l[jn * 2]);
                splitpack(h2, h3, A1h[jn * 2 + 1], A1l[jn * 2 + 1]);
            }

            // ---- layer 1: 64 -> 64 ----
            uint32_t A2h[16], A2l[16];
#pragma unroll
            for (int jn = 0; jn < 8; jn++) {
                float2 bia = *reinterpret_cast<const float2*>(sm + F_B1 + blk * 64 + jn * 8 + qq * 2);
                float D[4] = { bia.x, bia.y, bia.x, bia.y };
#pragma unroll
                for (int kb = 0; kb < 4; kb++) {
                    const uint2* tb = btab + (tb0 + 16 + (jn * 4 + kb) * 2) * 32 + lane;
                    uint2 bh = tb[0], bl = tb[32];
                    MMA4(D, (A1h + 4 * kb), bh.x, bh.y);
                    MMA4(D, (A1h + 4 * kb), bl.x, bl.y);
                    MMA4(D, (A1l + 4 * kb), bh.x, bh.y);
                }
                float h0 = fmaxf(D[0], 0.f), h1 = fmaxf(D[1], 0.f);
                float h2 = fmaxf(D[2], 0.f), h3 = fmaxf(D[3], 0.f);
                splitpack(h0, h1, A2h[jn * 2],     A2l[jn * 2]);
                splitpack(h2, h3, A2h[jn * 2 + 1], A2l[jn * 2 + 1]);
            }

            // ---- layer 2: 64 -> 8 ----
            {
                float2 bia = *reinterpret_cast<const float2*>(sm + F_B2 + blk * 8 + qq * 2);
                float D[4] = { bia.x, bia.y, bia.x, bia.y };
#pragma unroll
                for (int kb = 0; kb < 4; kb++) {
                    const uint2* tb = btab + (tb0 + 80 + kb * 2) * 32 + lane;
                    uint2 bh = tb[0], bl = tb[32];
                    MMA4(D, (A2h + 4 * kb), bh.x, bh.y);
                    MMA4(D, (A2h + 4 * kb), bl.x, bl.y);
                    MMA4(D, (A2l + 4 * kb), bh.x, bh.y);
                }
                sD[r * 8 + qq * 2]           = D[0];
                sD[r * 8 + qq * 2 + 1]       = D[1];
                sD[(r + 8) * 8 + qq * 2]     = D[2];
                sD[(r + 8) * 8 + qq * 2 + 1] = D[3];
            }
            __syncwarp();

            if (lane < 16) {
                float4 oa = *reinterpret_cast<float4*>(sD + lane * 8);
                float4 ob = *reinterpret_cast<float4*>(sD + lane * 8 + 4);
                float s0 = fast_tanh(oa.x), s1 = fast_tanh(oa.y);
                float s2 = fast_tanh(oa.z), s3 = fast_tanh(oa.w);
                logdet += s0 + s1 + s2 + s3;
                x[off2 + 0] = x[off2 + 0] * __expf(s0) + ob.x;
                x[off2 + 1] = x[off2 + 1] * __expf(s1) + ob.y;
                x[off2 + 2] = x[off2 + 2] * __expf(s2) + ob.z;
                x[off2 + 3] = x[off2 + 3] * __expf(s3) + ob.w;
            }
            __syncwarp();
        }

        if (lane < 16) {
            float ss = 0.f;
#pragma unroll
            for (int q = 0; q < 8; q++) ss += x[q] * x[q];
            out[token] = -0.5f * ss - 7.3515082656f + logdet;
        }
    }
}

// ============================================================================
extern "C" void kernel_launch(void* const* d_in, const int* in_sizes, int n_in,
                              void* d_out, int out_size)
{
    const float* latent = (const float*)d_in[0];
    const float* koop   = (const float*)d_in[1];
    const float* comm   = (const float*)d_in[2];
    const float* W0     = (const float*)d_in[3];
    const float* b0     = (const float*)d_in[4];
    const float* W1     = (const float*)d_in[5];
    const float* b1     = (const float*)d_in[6];
    const float* W2     = (const float*)d_in[7];
    const float* b2     = (const float*)d_in[8];
    float* out = (float*)d_out;

    eig_vals_kernel<<<C_COMM, 1>>>(koop);
    horner_kernel<<<C_COMM, 64>>>(koop);
    argmax_kernel<<<N_NODES / 256, 256>>>(comm);
    wprep_kernel<<<dim3(3, 11), 256>>>(W0, W1, W2);

    (void)cudaFuncSetAttribute(main_kernel,
                               cudaFuncAttributeMaxDynamicSharedMemorySize, SMEM_TOTAL);
    main_kernel<<<GRID_CTAS, 256, SMEM_TOTAL>>>(latent, b0, b1, b2, out);
}

// round 14
// speedup vs baseline: 1.3407x; 1.2524x over previous
#include <cuda_runtime.h>
#include <cuda_fp16.h>
#include <math.h>
#include <stdint.h>

#define N_NODES 4096
#define C_COMM  32
#define TOK     (32*4096*16)
#define NTILES  (TOK/16)        // 131072 warp-tiles of 16 tokens
#define GRID_CTAS 296
#define NWARPS  (GRID_CTAS*8)   // 2368

// ---------------- device scratch ----------------
__device__ float  g_G[C_COMM * 64];
__device__ int    g_cls[N_NODES];
__device__ double g_zr[C_COMM*8], g_zi[C_COMM*8], g_cr[C_COMM*8], g_ci[C_COMM*8];
// B-fragment tables: [3 blocks][88 pos][32 lanes] x uint2 (fp16 hi/lo pairs)
__device__ uint2  g_btab[3 * 88 * 32];

// ---------------- smem float layout ----------------
#define F_BTAB 0          // 16896 floats (btab as raw)
#define F_B0   16896      // 192
#define F_B1   17088      // 192
#define F_B2   17280      // 24
#define F_G    17304      // 2048
#define F_SIN  19352      // 8 warps x 16 x 16
#define F_SD   21400      // 8 warps x 16 x 8
#define SMEM_FLOATS 22424
#define SMEM_TOTAL  (SMEM_FLOATS*4)

// fp16 MMA: m16n8k16.f32.f16.f16.f32
#define MMA4(D, A, B0, B1) asm volatile( \
    "mma.sync.aligned.m16n8k16.row.col.f32.f16.f16.f32 " \
    "{%0,%1,%2,%3},{%4,%5,%6,%7},{%8,%9},{%0,%1,%2,%3};" \
    : "+f"((D)[0]), "+f"((D)[1]), "+f"((D)[2]), "+f"((D)[3]) \
    : "r"((A)[0]), "r"((A)[1]), "r"((A)[2]), "r"((A)[3]), "r"(B0), "r"(B1))

__device__ __forceinline__ uint32_t h2pack(float v0, float v1) {
    __half2 h = __floats2half2_rn(v0, v1);     // .x = v0 (low 16)
    return *reinterpret_cast<uint32_t*>(&h);
}

// fast transcendentals (MUFU-based)
__device__ __forceinline__ float fast_tanh(float x) {
    float e = __expf(2.f * x);
    return 1.f - __fdividef(2.f, e + 1.f);
}

// ============================================================================
// Kernel 1a: fp32 Hessenberg + Francis QR eigenvalues, fp64 Newton coeffs
// ============================================================================
__global__ void eig_vals_kernel(const float* __restrict__ koop)
{
    int c = blockIdx.x;
    if (threadIdx.x != 0) return;
    float a[8][8];
    for (int i = 0; i < 8; i++)
        for (int j = 0; j < 8; j++)
            a[i][j] = koop[c * 64 + i * 8 + j];
    for (int k = 0; k < 6; k++) {
        float nx = 0.f;
        for (int i = k + 1; i < 8; i++) nx += a[i][k] * a[i][k];
        nx = sqrtf(nx);
        if (nx < 1e-30f) continue;
        float x0 = a[k + 1][k];
        float alpha = (x0 >= 0.f) ? -nx : nx;
        float v[8];
        for (int i = 0; i < 8; i++) v[i] = 0.f;
        v[k + 1] = x0 - alpha;
        for (int i = k + 2; i < 8; i++) v[i] = a[i][k];
        float vv = 0.f;
        for (int i = k + 1; i < 8; i++) vv += v[i] * v[i];
        if (vv < 1e-30f) continue;
        float beta = 2.f / vv;
        for (int j = 0; j < 8; j++) {
            float s = 0.f;
            for (int i = k + 1; i < 8; i++) s += v[i] * a[i][j];
            s *= beta;
            for (int i = k + 1; i < 8; i++) a[i][j] -= v[i] * s;
        }
        for (int i = 0; i < 8; i++) {
            float s = 0.f;
            for (int j = k + 1; j < 8; j++) s += a[i][j] * v[j];
            s *= beta;
            for (int j = k + 1; j < 8; j++) a[i][j] -= s * v[j];
        }
    }
    float wr[8], wi[8];
    float anorm = 0.f;
    for (int i = 0; i < 8; i++) {
        int j0 = (i - 1 > 0) ? (i - 1) : 0;
        for (int j = j0; j < 8; j++) anorm += fabsf(a[i][j]);
    }
    const float EPSF = 1.1920929e-07f;
    int nn = 7; float t = 0.f; int guard = 0;
    while (nn >= 0 && guard < 2000) {
        int its = 0, l = 0;
        do {
            guard++;
            if (guard >= 2000) { wr[nn] = a[nn][nn] + t; wi[nn] = 0.f; nn--; break; }
            for (l = nn; l >= 1; l--) {
                float s = fabsf(a[l - 1][l - 1]) + fabsf(a[l][l]);
                if (s == 0.f) s = anorm;
                if (fabsf(a[l][l - 1]) <= EPSF * s) { a[l][l - 1] = 0.f; break; }
            }
            if (l < 0) l = 0;
            float x = a[nn][nn];
            if (l == nn) { wr[nn] = x + t; wi[nn] = 0.f; nn--; }
            else {
                float y = a[nn - 1][nn - 1];
                float w = a[nn][nn - 1] * a[nn - 1][nn];
                if (l == nn - 1) {
                    float p = 0.5f * (y - x);
                    float q = p * p + w;
                    float z = sqrtf(fabsf(q));
                    x += t;
                    if (q >= 0.f) {
                        z = p + ((p >= 0.f) ? z : -z);
                        wr[nn - 1] = wr[nn] = x + z;
                        if (z != 0.f) wr[nn] = x - w / z;
                        wi[nn - 1] = wi[nn] = 0.f;
                    } else {
                        wr[nn - 1] = wr[nn] = x + p;
                        wi[nn] = z; wi[nn - 1] = -z;
                    }
                    nn -= 2;
                } else {
                    float p = 0.f, q = 0.f, r = 0.f, z, s, u, v;
                    if (its == 10 || its == 20) {
                        t += x;
                        for (int i = 0; i <= nn; i++) a[i][i] -= x;
                        s = fabsf(a[nn][nn - 1]) + fabsf(a[nn - 1][nn - 2]);
                        y = x = 0.75f * s;
                        w = -0.4375f * s * s;
                    }
                    its++;
                    if (its > 50) { wr[nn] = a[nn][nn] + t; wi[nn] = 0.f; nn--; break; }
                    int m;
                    for (m = nn - 2; m >= l; m--) {
                        z = a[m][m]; r = x - z; s = y - z;
                        p = (r * s - w) / a[m + 1][m] + a[m][m + 1];
                        q = a[m + 1][m + 1] - z - r - s;
                        r = a[m + 2][m + 1];
                        s = fabsf(p) + fabsf(q) + fabsf(r);
                        p /= s; q /= s; r /= s;
                        if (m == l) break;
                        u = fabsf(a[m][m - 1]) * (fabsf(q) + fabsf(r));
                        v = fabsf(p) * (fabsf(a[m - 1][m - 1]) + fabsf(z) + fabsf(a[m + 1][m + 1]));
                        if (u <= EPSF * v) break;
                    }
                    for (int i = m + 2; i <= nn; i++) {
                        a[i][i - 2] = 0.f;
                        if (i != m + 2) a[i][i - 3] = 0.f;
                    }
                    for (int k = m; k <= nn - 1; k++) {
                        if (k != m) {
                            p = a[k][k - 1]; q = a[k + 1][k - 1];
                            r = (k != nn - 1) ? a[k + 2][k - 1] : 0.f;
                            x = fabsf(p) + fabsf(q) + fabsf(r);
                            if (x != 0.f) { p /= x; q /= x; r /= x; }
                        }
                        s = sqrtf(p * p + q * q + r * r);
                        if (p < 0.f) s = -s;
                        if (s != 0.f) {
                            if (k == m) { if (l != m) a[k][k - 1] = -a[k][k - 1]; }
                            else a[k][k - 1] = -s * x;
                            p += s; x = p / s; y = q / s; z = r / s; q /= p; r /= p;
                            for (int j = k; j <= nn; j++) {
                                float pp = a[k][j] + q * a[k + 1][j];
                                if (k != nn - 1) { pp += r * a[k + 2][j]; a[k + 2][j] -= pp * z; }
                                a[k + 1][j] -= pp * y;
                                a[k][j]     -= pp * x;
                            }
                            int mmin = (nn < k + 3) ? nn : (k + 3);
                            for (int i = l; i <= mmin; i++) {
                                float pp = x * a[i][k] + y * a[i][k + 1];
                                if (k != nn - 1) { pp += z * a[i][k + 2]; a[i][k + 2] -= pp * r; }
                                a[i][k + 1] -= pp * q;
                                a[i][k]     -= pp;
                            }
                        }
                    }
                }
            }
        } while (l < nn - 1);
    }
    double zr[8], zi[8];
    for (int i = 0; i < 8; i++) { zr[i] = (double)wr[i] + 1e-10; zi[i] = (double)wi[i] + 1e-10; }
    bool mask[8]; bool any = false;
    for (int i = 0; i < 8; i++) {
        double am = sqrt(zr[i] * zr[i] + zi[i] * zi[i]);
        mask[i] = (am <= 1.1 && am >= 0.9);
        any = any || mask[i];
    }
    if (!any) for (int i = 0; i < 8; i++) mask[i] = true;
    for (int i = 1; i < 8; i++)
        for (int j = 0; j < i; j++)
            if (fabs(zr[i] - zr[j]) < 1e-9 && fabs(zi[i] - zi[j]) < 1e-9) {
                zr[i] += 1.0e-8 * (i + 1);
                zi[i] += 0.7e-8 * (i + 1);
            }
    double cr[8], ci[8];
    for (int i = 0; i < 8; i++) {
        cr[i] = mask[i] ? zr[i] : 0.0;
        ci[i] = mask[i] ? zi[i] : 0.0;
    }
    for (int j = 1; j < 8; j++)
        for (int i = 7; i >= j; i--) {
            double nr = cr[i] - cr[i - 1], ni = ci[i] - ci[i - 1];
            double dr = zr[i] - zr[i - j], di = zi[i] - zi[i - j];
            double d2 = dr * dr + di * di;
            cr[i] = (nr * dr + ni * di) / d2;
            ci[i] = (ni * dr - nr * di) / d2;
        }
    for (int i = 0; i < 8; i++) {
        g_zr[c * 8 + i] = zr[i]; g_zi[c * 8 + i] = zi[i];
        g_cr[c * 8 + i] = cr[i]; g_ci[c * 8 + i] = ci[i];
    }
}

// ============================================================================
// Kernel 1b: parallel complex Horner p(A) -> G (64 threads per matrix, fp64)
// ============================================================================
__global__ void horner_kernel(const float* __restrict__ koop)
{
    int c = blockIdx.x;
    int t = threadIdx.x;
    int i = t >> 3, j = t & 7;
    __shared__ double sA[64], sMr[64], sMi[64], szr[8], szi[8], scr[8], sci[8];
    sA[t] = (double)koop[c * 64 + t];
    if (t < 8) {
        szr[t] = g_zr[c * 8 + t]; szi[t] = g_zi[c * 8 + t];
        scr[t] = g_cr[c * 8 + t]; sci[t] = g_ci[c * 8 + t];
    }
    __syncthreads();
    double mr = (i == j) ? scr[7] : 0.0;
    double mi = (i == j) ? sci[7] : 0.0;
    sMr[t] = mr; sMi[t] = mi;
    __syncthreads();
    for (int k = 6; k >= 0; k--) {
        double tr = 0.0, ti = 0.0;
#pragma unroll
        for (int q = 0; q < 8; q++) {
            tr += sA[i * 8 + q] * sMr[q * 8 + j];
            ti += sA[i * 8 + q] * sMi[q * 8 + j];
        }
        double omr = mr, omi = mi;
        __syncthreads();
        mr = tr - (szr[k] * omr - szi[k] * omi) + ((i == j) ? scr[k] : 0.0);
        mi = ti - (szr[k] * omi + szi[k] * omr) + ((i == j) ? sci[k] : 0.0);
        sMr[t] = mr; sMi[t] = mi;
        __syncthreads();
    }
    g_G[c * 64 + t] = (float)mr;
}

// ============================================================================
// Kernel 2: community argmax
// ============================================================================
__global__ void argmax_kernel(const float* __restrict__ comm)
{
    int n = blockIdx.x * blockDim.x + threadIdx.x;
    if (n >= N_NODES) return;
    float best = comm[n * C_COMM];
    int bi = 0;
#pragma unroll
    for (int cc = 1; cc < C_COMM; cc++) {
        float v = comm[n * C_COMM + cc];
        if (v > best) { best = v; bi = cc; }
    }
    g_cls[n] = bi;
}

// ============================================================================
// Kernel 3: build per-lane B-fragment tables (fp16 hi/lo, m16n8k16 layout).
// grid = (3 blocks, 11 slabs). B = Bhi + Blo exact to ~2^-22.
// ============================================================================
__global__ void wprep_kernel(const float* __restrict__ W0,
                             const float* __restrict__ W1,
                             const float* __restrict__ W2)
{
    int blk = blockIdx.x;
    int idx = blockIdx.y * 256 + threadIdx.x;
    if (idx >= 88 * 32) return;
    {
        int pos = idx >> 5, lane = idx & 31;
        int v, jn, kb, layer;
        if (pos < 16)      { layer = 0; v = pos & 1; jn = pos >> 1; kb = 0; }
        else if (pos < 80) { int p = pos - 16; v = p & 1; int q = p >> 1; kb = q & 3; jn = q >> 2; layer = 1; }
        else               { int p = pos - 80; v = p & 1; kb = p >> 1; jn = 0; layer = 2; }
        int n = jn * 8 + (lane >> 2);
        int k0 = 16 * kb + 2 * (lane & 3);
        float w[4];
#pragma unroll
        for (int e = 0; e < 4; e++) {
            int k = k0 + (e >> 1) * 8 + (e & 1);
            float val = 0.f;
            if (layer == 0)      { if (k < 12) val = W0[blk * 768 + k * 64 + n]; }
            else if (layer == 1) { val = W1[blk * 4096 + k * 64 + n]; }
            else                 { val = W2[blk * 512 + k * 8 + n]; }
            __half bh = __float2half_rn(val);
            if (v == 0) w[e] = __half2float(bh);
            else        w[e] = __half2float(__float2half_rn(val - __half2float(bh)));
        }
        uint32_t px = ((uint32_t)__half_as_ushort(__float2half_rn(w[1])) << 16)
                    |  (uint32_t)__half_as_ushort(__float2half_rn(w[0]));
        uint32_t py = ((uint32_t)__half_as_ushort(__float2half_rn(w[3])) << 16)
                    |  (uint32_t)__half_as_ushort(__float2half_rn(w[2]));
        g_btab[(blk * 88 + pos) * 32 + lane] = make_uint2(px, py);
    }
}

// ============================================================================
// Kernel 4: main fused flow via fp16 mma.sync, A single fp16 + B hi/lo split.
// Persistent, warp = 16 tokens. 264 MMAs/tile (was 396), no A-lo fragments.
// ============================================================================
__global__ void __launch_bounds__(256, 2) main_kernel(
    const float* __restrict__ latent,
    const float* __restrict__ b0g, const float* __restrict__ b1g,
    const float* __restrict__ b2g, float* __restrict__ out)
{
    extern __shared__ float sm[];
    {
        const uint4* src = reinterpret_cast<const uint4*>(g_btab);
        uint4* dst = reinterpret_cast<uint4*>(sm);
        for (int i = threadIdx.x; i < 16896 / 4; i += 256) dst[i] = src[i];
        for (int i = threadIdx.x; i < 192;  i += 256) sm[F_B0 + i] = b0g[i];
        for (int i = threadIdx.x; i < 192;  i += 256) sm[F_B1 + i] = b1g[i];
        for (int i = threadIdx.x; i < 24;   i += 256) sm[F_B2 + i] = b2g[i];
        for (int i = threadIdx.x; i < 2048; i += 256) sm[F_G + i] = g_G[i];
    }
    __syncthreads();

    const int wid = threadIdx.x >> 5;
    const int lane = threadIdx.x & 31;
    const int r = lane >> 2, qq = lane & 3;
    float* stg = sm + F_SIN + wid * 256;
    float* sD  = sm + F_SD  + wid * 128;
    const uint2* btab = reinterpret_cast<const uint2*>(sm);
    const int warpGlobal = blockIdx.x * 8 + wid;

    for (int tile = warpGlobal; tile < NTILES; tile += NWARPS) {
        const int token = tile * 16 + lane;
        float x[8], cond[8];
        if (lane < 16) {
            const float4* lat4 = reinterpret_cast<const float4*>(latent);
            float4 p0 = lat4[token * 2], p1 = lat4[token * 2 + 1];
            x[0] = p0.x; x[1] = p0.y; x[2] = p0.z; x[3] = p0.w;
            x[4] = p1.x; x[5] = p1.y; x[6] = p1.z; x[7] = p1.w;
            const int cls = g_cls[(token >> 4) & (N_NODES - 1)];
            const float* sG = sm + F_G + cls * 64;
#pragma unroll
            for (int e = 0; e < 8; e++) cond[e] = 0.f;
#pragma unroll
            for (int d = 0; d < 8; d++) {
                float xd = x[d];
#pragma unroll
                for (int e = 0; e < 8; e++) cond[e] = fmaf(xd, sG[d * 8 + e], cond[e]);
            }
        }
        float logdet = 0.f;

#pragma unroll 1
        for (int blk = 0; blk < 3; blk++) {
            const int off1 = (blk & 1) ? 4 : 0;
            const int off2 = 4 - off1;
            const int tb0 = blk * 88;

            if (lane < 16) {
#pragma unroll
                for (int q = 0; q < 4; q++) stg[lane * 16 + q] = x[off1 + q];
#pragma unroll
                for (int q = 0; q < 8; q++) stg[lane * 16 + 4 + q] = cond[q];
            }
            __syncwarp();

            uint32_t Ah[4];
            {
                float2 p00 = *reinterpret_cast<float2*>(stg + r * 16 + qq * 2);
                float2 p10 = *reinterpret_cast<float2*>(stg + (r + 8) * 16 + qq * 2);
                float2 p08 = make_float2(0.f, 0.f), p18 = p08;
                if (qq < 2) {
                    p08 = *reinterpret_cast<float2*>(stg + r * 16 + qq * 2 + 8);
                    p18 = *reinterpret_cast<float2*>(stg + (r + 8) * 16 + qq * 2 + 8);
                }
                Ah[0] = h2pack(p00.x, p00.y);
                Ah[1] = h2pack(p10.x, p10.y);
                Ah[2] = h2pack(p08.x, p08.y);
                Ah[3] = h2pack(p18.x, p18.y);
            }
            __syncwarp();

            // ---- layer 0: 12(->16) -> 64 ----
            uint32_t A1h[16];
#pragma unroll
            for (int jn = 0; jn < 8; jn++) {
                float2 bia = *reinterpret_cast<const float2*>(sm + F_B0 + blk * 64 + jn * 8 + qq * 2);
                float D[4] = { bia.x, bia.y, bia.x, bia.y };
                const uint2* tb = btab + (tb0 + jn * 2) * 32 + lane;
                uint2 bh = tb[0], bl = tb[32];
                MMA4(D, Ah, bh.x, bh.y);
                MMA4(D, Ah, bl.x, bl.y);
                float h0 = fmaxf(D[0], 0.f), h1 = fmaxf(D[1], 0.f);
                float h2 = fmaxf(D[2], 0.f), h3 = fmaxf(D[3], 0.f);
                A1h[jn * 2]     = h2pack(h0, h1);
                A1h[jn * 2 + 1] = h2pack(h2, h3);
            }

            // ---- layer 1: 64 -> 64 ----
            uint32_t A2h[16];
#pragma unroll
            for (int jn = 0; jn < 8; jn++) {
                float2 bia = *reinterpret_cast<const float2*>(sm + F_B1 + blk * 64 + jn * 8 + qq * 2);
                float D[4] = { bia.x, bia.y, bia.x, bia.y };
#pragma unroll
                for (int kb = 0; kb < 4; kb++) {
                    const uint2* tb = btab + (tb0 + 16 + (jn * 4 + kb) * 2) * 32 + lane;
                    uint2 bh = tb[0], bl = tb[32];
                    MMA4(D, (A1h + 4 * kb), bh.x, bh.y);
                    MMA4(D, (A1h + 4 * kb), bl.x, bl.y);
                }
                float h0 = fmaxf(D[0], 0.f), h1 = fmaxf(D[1], 0.f);
                float h2 = fmaxf(D[2], 0.f), h3 = fmaxf(D[3], 0.f);
                A2h[jn * 2]     = h2pack(h0, h1);
                A2h[jn * 2 + 1] = h2pack(h2, h3);
            }

            // ---- layer 2: 64 -> 8 ----
            {
                float2 bia = *reinterpret_cast<const float2*>(sm + F_B2 + blk * 8 + qq * 2);
                float D[4] = { bia.x, bia.y, bia.x, bia.y };
#pragma unroll
                for (int kb = 0; kb < 4; kb++) {
                    const uint2* tb = btab + (tb0 + 80 + kb * 2) * 32 + lane;
                    uint2 bh = tb[0], bl = tb[32];
                    MMA4(D, (A2h + 4 * kb), bh.x, bh.y);
                    MMA4(D, (A2h + 4 * kb), bl.x, bl.y);
                }
                sD[r * 8 + qq * 2]           = D[0];
                sD[r * 8 + qq * 2 + 1]       = D[1];
                sD[(r + 8) * 8 + qq * 2]     = D[2];
                sD[(r + 8) * 8 + qq * 2 + 1] = D[3];
            }
            __syncwarp();

            if (lane < 16) {
                float4 oa = *reinterpret_cast<float4*>(sD + lane * 8);
                float4 ob = *reinterpret_cast<float4*>(sD + lane * 8 + 4);
                float s0 = fast_tanh(oa.x), s1 = fast_tanh(oa.y);
                float s2 = fast_tanh(oa.z), s3 = fast_tanh(oa.w);
                logdet += s0 + s1 + s2 + s3;
                x[off2 + 0] = x[off2 + 0] * __expf(s0) + ob.x;
                x[off2 + 1] = x[off2 + 1] * __expf(s1) + ob.y;
                x[off2 + 2] = x[off2 + 2] * __expf(s2) + ob.z;
                x[off2 + 3] = x[off2 + 3] * __expf(s3) + ob.w;
            }
            __syncwarp();
        }

        if (lane < 16) {
            float ss = 0.f;
#pragma unroll
            for (int q = 0; q < 8; q++) ss += x[q] * x[q];
            out[token] = -0.5f * ss - 7.3515082656f + logdet;
        }
    }
}

// ============================================================================
extern "C" void kernel_launch(void* const* d_in, const int* in_sizes, int n_in,
                              void* d_out, int out_size)
{
    const float* latent = (const float*)d_in[0];
    const float* koop   = (const float*)d_in[1];
    const float* comm   = (const float*)d_in[2];
    const float* W0     = (const float*)d_in[3];
    const float* b0     = (const float*)d_in[4];
    const float* W1     = (const float*)d_in[5];
    const float* b1     = (const float*)d_in[6];
    const float* W2     = (const float*)d_in[7];
    const float* b2     = (const float*)d_in[8];
    float* out = (float*)d_out;

    eig_vals_kernel<<<C_COMM, 1>>>(koop);
    horner_kernel<<<C_COMM, 64>>>(koop);
    argmax_kernel<<<N_NODES / 256, 256>>>(comm);
    wprep_kernel<<<dim3(3, 11), 256>>>(W0, W1, W2);

    (void)cudaFuncSetAttribute(main_kernel,
                               cudaFuncAttributeMaxDynamicSharedMemorySize, SMEM_TOTAL);
    main_kernel<<<GRID_CTAS, 256, SMEM_TOTAL>>>(latent, b0, b1, b2, out);
}

// round 15
// speedup vs baseline: 1.7939x; 1.3380x over previous
#include <cuda_runtime.h>
#include <cuda_fp16.h>
#include <math.h>
#include <stdint.h>

#define N_NODES 4096
#define C_COMM  32
#define TOK     (32*4096*16)
#define NTILES  (TOK/16)        // 131072 warp-tiles of 16 tokens
#define GRID_CTAS 296
#define NWARPS  (GRID_CTAS*8)   // 2368

// ---------------- device scratch ----------------
__device__ float  g_G[C_COMM * 64];
__device__ int    g_cls[N_NODES];
__device__ double g_zr[C_COMM*8], g_zi[C_COMM*8], g_cr[C_COMM*8], g_ci[C_COMM*8];
// B-fragment tables: [3 blocks][44 pos][32 lanes] x uint2 (single fp16)
__device__ uint2  g_btab[3 * 44 * 32];

// ---------------- smem float layout ----------------
#define F_BTAB 0          // 8448 floats (btab as raw)
#define F_B0   8448       // 192
#define F_B1   8640       // 192
#define F_B2   8832       // 24
#define F_G    8856       // 2048
#define F_SIN  10904      // 8 warps x 16 x 16
#define F_SD   12952      // 8 warps x 16 x 8
#define SMEM_FLOATS 13976
#define SMEM_TOTAL  (SMEM_FLOATS*4)

// fp16 MMA: m16n8k16.f32.f16.f16.f32
#define MMA4(D, A, B0, B1) asm volatile( \
    "mma.sync.aligned.m16n8k16.row.col.f32.f16.f16.f32 " \
    "{%0,%1,%2,%3},{%4,%5,%6,%7},{%8,%9},{%0,%1,%2,%3};" \
    : "+f"((D)[0]), "+f"((D)[1]), "+f"((D)[2]), "+f"((D)[3]) \
    : "r"((A)[0]), "r"((A)[1]), "r"((A)[2]), "r"((A)[3]), "r"(B0), "r"(B1))

__device__ __forceinline__ uint32_t h2pack(float v0, float v1) {
    __half2 h = __floats2half2_rn(v0, v1);     // .x = v0 (low 16)
    return *reinterpret_cast<uint32_t*>(&h);
}

// fast transcendentals (MUFU-based)
__device__ __forceinline__ float fast_tanh(float x) {
    float e = __expf(2.f * x);
    return 1.f - __fdividef(2.f, e + 1.f);
}

// ============================================================================
// Kernel 1a: fp32 Hessenberg + Francis QR eigenvalues, fp64 Newton coeffs
// ============================================================================
__global__ void eig_vals_kernel(const float* __restrict__ koop)
{
    int c = blockIdx.x;
    if (threadIdx.x != 0) return;
    float a[8][8];
    for (int i = 0; i < 8; i++)
        for (int j = 0; j < 8; j++)
            a[i][j] = koop[c * 64 + i * 8 + j];
    for (int k = 0; k < 6; k++) {
        float nx = 0.f;
        for (int i = k + 1; i < 8; i++) nx += a[i][k] * a[i][k];
        nx = sqrtf(nx);
        if (nx < 1e-30f) continue;
        float x0 = a[k + 1][k];
        float alpha = (x0 >= 0.f) ? -nx : nx;
        float v[8];
        for (int i = 0; i < 8; i++) v[i] = 0.f;
        v[k + 1] = x0 - alpha;
        for (int i = k + 2; i < 8; i++) v[i] = a[i][k];
        float vv = 0.f;
        for (int i = k + 1; i < 8; i++) vv += v[i] * v[i];
        if (vv < 1e-30f) continue;
        float beta = 2.f / vv;
        for (int j = 0; j < 8; j++) {
            float s = 0.f;
            for (int i = k + 1; i < 8; i++) s += v[i] * a[i][j];
            s *= beta;
            for (int i = k + 1; i < 8; i++) a[i][j] -= v[i] * s;
        }
        for (int i = 0; i < 8; i++) {
            float s = 0.f;
            for (int j = k + 1; j < 8; j++) s += a[i][j] * v[j];
            s *= beta;
            for (int j = k + 1; j < 8; j++) a[i][j] -= s * v[j];
        }
    }
    float wr[8], wi[8];
    float anorm = 0.f;
    for (int i = 0; i < 8; i++) {
        int j0 = (i - 1 > 0) ? (i - 1) : 0;
        for (int j = j0; j < 8; j++) anorm += fabsf(a[i][j]);
    }
    const float EPSF = 1.1920929e-07f;
    int nn = 7; float t = 0.f; int guard = 0;
    while (nn >= 0 && guard < 2000) {
        int its = 0, l = 0;
        do {
            guard++;
            if (guard >= 2000) { wr[nn] = a[nn][nn] + t; wi[nn] = 0.f; nn--; break; }
            for (l = nn; l >= 1; l--) {
                float s = fabsf(a[l - 1][l - 1]) + fabsf(a[l][l]);
                if (s == 0.f) s = anorm;
                if (fabsf(a[l][l - 1]) <= EPSF * s) { a[l][l - 1] = 0.f; break; }
            }
            if (l < 0) l = 0;
            float x = a[nn][nn];
            if (l == nn) { wr[nn] = x + t; wi[nn] = 0.f; nn--; }
            else {
                float y = a[nn - 1][nn - 1];
                float w = a[nn][nn - 1] * a[nn - 1][nn];
                if (l == nn - 1) {
                    float p = 0.5f * (y - x);
                    float q = p * p + w;
                    float z = sqrtf(fabsf(q));
                    x += t;
                    if (q >= 0.f) {
                        z = p + ((p >= 0.f) ? z : -z);
                        wr[nn - 1] = wr[nn] = x + z;
                        if (z != 0.f) wr[nn] = x - w / z;
                        wi[nn - 1] = wi[nn] = 0.f;
                    } else {
                        wr[nn - 1] = wr[nn] = x + p;
                        wi[nn] = z; wi[nn - 1] = -z;
                    }
                    nn -= 2;
                } else {
                    float p = 0.f, q = 0.f, r = 0.f, z, s, u, v;
                    if (its == 10 || its == 20) {
                        t += x;
                        for (int i = 0; i <= nn; i++) a[i][i] -= x;
                        s = fabsf(a[nn][nn - 1]) + fabsf(a[nn - 1][nn - 2]);
                        y = x = 0.75f * s;
                        w = -0.4375f * s * s;
                    }
                    its++;
                    if (its > 50) { wr[nn] = a[nn][nn] + t; wi[nn] = 0.f; nn--; break; }
                    int m;
                    for (m = nn - 2; m >= l; m--) {
                        z = a[m][m]; r = x - z; s = y - z;
                        p = (r * s - w) / a[m + 1][m] + a[m][m + 1];
                        q = a[m + 1][m + 1] - z - r - s;
                        r = a[m + 2][m + 1];
                        s = fabsf(p) + fabsf(q) + fabsf(r);
                        p /= s; q /= s; r /= s;
                        if (m == l) break;
                        u = fabsf(a[m][m - 1]) * (fabsf(q) + fabsf(r));
                        v = fabsf(p) * (fabsf(a[m - 1][m - 1]) + fabsf(z) + fabsf(a[m + 1][m + 1]));
                        if (u <= EPSF * v) break;
                    }
                    for (int i = m + 2; i <= nn; i++) {
                        a[i][i - 2] = 0.f;
                        if (i != m + 2) a[i][i - 3] = 0.f;
                    }
                    for (int k = m; k <= nn - 1; k++) {
                        if (k != m) {
                            p = a[k][k - 1]; q = a[k + 1][k - 1];
                            r = (k != nn - 1) ? a[k + 2][k - 1] : 0.f;
                            x = fabsf(p) + fabsf(q) + fabsf(r);
                            if (x != 0.f) { p /= x; q /= x; r /= x; }
                        }
                        s = sqrtf(p * p + q * q + r * r);
                        if (p < 0.f) s = -s;
                        if (s != 0.f) {
                            if (k == m) { if (l != m) a[k][k - 1] = -a[k][k - 1]; }
                            else a[k][k - 1] = -s * x;
                            p += s; x = p / s; y = q / s; z = r / s; q /= p; r /= p;
                            for (int j = k; j <= nn; j++) {
                                float pp = a[k][j] + q * a[k + 1][j];
                                if (k != nn - 1) { pp += r * a[k + 2][j]; a[k + 2][j] -= pp * z; }
                                a[k + 1][j] -= pp * y;
                                a[k][j]     -= pp * x;
                            }
                            int mmin = (nn < k + 3) ? nn : (k + 3);
                            for (int i = l; i <= mmin; i++) {
                                float pp = x * a[i][k] + y * a[i][k + 1];
                                if (k != nn - 1) { pp += z * a[i][k + 2]; a[i][k + 2] -= pp * r; }
                                a[i][k + 1] -= pp * q;
                                a[i][k]     -= pp;
                            }
                        }
                    }
                }
            }
        } while (l < nn - 1);
    }
    double zr[8], zi[8];
    for (int i = 0; i < 8; i++) { zr[i] = (double)wr[i] + 1e-10; zi[i] = (double)wi[i] + 1e-10; }
    bool mask[8]; bool any = false;
    for (int i = 0; i < 8; i++) {
        double am = sqrt(zr[i] * zr[i] + zi[i] * zi[i]);
        mask[i] = (am <= 1.1 && am >= 0.9);
        any = any || mask[i];
    }
    if (!any) for (int i = 0; i < 8; i++) mask[i] = true;
    for (int i = 1; i < 8; i++)
        for (int j = 0; j < i; j++)
            if (fabs(zr[i] - zr[j]) < 1e-9 && fabs(zi[i] - zi[j]) < 1e-9) {
                zr[i] += 1.0e-8 * (i + 1);
                zi[i] += 0.7e-8 * (i + 1);
            }
    double cr[8], ci[8];
    for (int i = 0; i < 8; i++) {
        cr[i] = mask[i] ? zr[i] : 0.0;
        ci[i] = mask[i] ? zi[i] : 0.0;
    }
    for (int j = 1; j < 8; j++)
        for (int i = 7; i >= j; i--) {
            double nr = cr[i] - cr[i - 1], ni = ci[i] - ci[i - 1];
            double dr = zr[i] - zr[i - j], di = zi[i] - zi[i - j];
            double d2 = dr * dr + di * di;
            cr[i] = (nr * dr + ni * di) / d2;
            ci[i] = (ni * dr - nr * di) / d2;
        }
    for (int i = 0; i < 8; i++) {
        g_zr[c * 8 + i] = zr[i]; g_zi[c * 8 + i] = zi[i];
        g_cr[c * 8 + i] = cr[i]; g_ci[c * 8 + i] = ci[i];
    }
}

// ============================================================================
// Kernel 1b: parallel complex Horner p(A) -> G (64 threads per matrix, fp64)
// ============================================================================
__global__ void horner_kernel(const float* __restrict__ koop)
{
    int c = blockIdx.x;
    int t = threadIdx.x;
    int i = t >> 3, j = t & 7;
    __shared__ double sA[64], sMr[64], sMi[64], szr[8], szi[8], scr[8], sci[8];
    sA[t] = (double)koop[c * 64 + t];
    if (t < 8) {
        szr[t] = g_zr[c * 8 + t]; szi[t] = g_zi[c * 8 + t];
        scr[t] = g_cr[c * 8 + t]; sci[t] = g_ci[c * 8 + t];
    }
    __syncthreads();
    double mr = (i == j) ? scr[7] : 0.0;
    double mi = (i == j) ? sci[7] : 0.0;
    sMr[t] = mr; sMi[t] = mi;
    __syncthreads();
    for (int k = 6; k >= 0; k--) {
        double tr = 0.0, ti = 0.0;
#pragma unroll
        for (int q = 0; q < 8; q++) {
            tr += sA[i * 8 + q] * sMr[q * 8 + j];
            ti += sA[i * 8 + q] * sMi[q * 8 + j];
        }
        double omr = mr, omi = mi;
        __syncthreads();
        mr = tr - (szr[k] * omr - szi[k] * omi) + ((i == j) ? scr[k] : 0.0);
        mi = ti - (szr[k] * omi + szi[k] * omr) + ((i == j) ? sci[k] : 0.0);
        sMr[t] = mr; sMi[t] = mi;
        __syncthreads();
    }
    g_G[c * 64 + t] = (float)mr;
}

// ============================================================================
// Kernel 2: community argmax
// ============================================================================
__global__ void argmax_kernel(const float* __restrict__ comm)
{
    int n = blockIdx.x * blockDim.x + threadIdx.x;
    if (n >= N_NODES) return;
    float best = comm[n * C_COMM];
    int bi = 0;
#pragma unroll
    for (int cc = 1; cc < C_COMM; cc++) {
        float v = comm[n * C_COMM + cc];
        if (v > best) { best = v; bi = cc; }
    }
    g_cls[n] = bi;
}

// ============================================================================
// Kernel 3: build per-lane B-fragment tables (single fp16, m16n8k16 layout).
// grid = (3 blocks, 6 slabs). pos map per block (44 pos):
// L0: jn (8) | L1: 8 + jn*4+kb (32) | L2: 40 + kb (4).
// Fragment: x = pack(W[k0][n], W[k1][n]), y = pack(W[k0+8][n], W[k1+8][n]);
// n = jn*8+lane/4, k0 = 16*kb+2*(lane%4).
// ============================================================================
__global__ void wprep_kernel(const float* __restrict__ W0,
                             const float* __restrict__ W1,
                             const float* __restrict__ W2)
{
    int blk = blockIdx.x;
    int idx = blockIdx.y * 256 + threadIdx.x;
    if (idx >= 44 * 32) return;
    {
        int pos = idx >> 5, lane = idx & 31;
        int jn, kb, layer;
        if (pos < 8)       { layer = 0; jn = pos; kb = 0; }
        else if (pos < 40) { int p = pos - 8; kb = p & 3; jn = p >> 2; layer = 1; }
        else               { layer = 2; kb = pos - 40; jn = 0; }
        int n = jn * 8 + (lane >> 2);
        int k0 = 16 * kb + 2 * (lane & 3);
        __half w[4];
#pragma unroll
        for (int e = 0; e < 4; e++) {
            int k = k0 + (e >> 1) * 8 + (e & 1);
            float val = 0.f;
            if (layer == 0)      { if (k < 12) val = W0[blk * 768 + k * 64 + n]; }
            else if (layer == 1) { val = W1[blk * 4096 + k * 64 + n]; }
            else                 { val = W2[blk * 512 + k * 8 + n]; }
            w[e] = __float2half_rn(val);
        }
        uint32_t px = ((uint32_t)__half_as_ushort(w[1]) << 16)
                    |  (uint32_t)__half_as_ushort(w[0]);
        uint32_t py = ((uint32_t)__half_as_ushort(w[3]) << 16)
                    |  (uint32_t)__half_as_ushort(w[2]);
        g_btab[(blk * 44 + pos) * 32 + lane] = make_uint2(px, py);
    }
}

// ============================================================================
// Kernel 4: main fused flow via fp16 mma.sync, A and B single fp16.
// Persistent, warp = 16 tokens. 132 MMAs/tile (was 264).
// ============================================================================
__global__ void __launch_bounds__(256, 2) main_kernel(
    const float* __restrict__ latent,
    const float* __restrict__ b0g, const float* __restrict__ b1g,
    const float* __restrict__ b2g, float* __restrict__ out)
{
    extern __shared__ float sm[];
    {
        const uint4* src = reinterpret_cast<const uint4*>(g_btab);
        uint4* dst = reinterpret_cast<uint4*>(sm);
        for (int i = threadIdx.x; i < 8448 / 4; i += 256) dst[i] = src[i];
        for (int i = threadIdx.x; i < 192;  i += 256) sm[F_B0 + i] = b0g[i];
        for (int i = threadIdx.x; i < 192;  i += 256) sm[F_B1 + i] = b1g[i];
        for (int i = threadIdx.x; i < 24;   i += 256) sm[F_B2 + i] = b2g[i];
        for (int i = threadIdx.x; i < 2048; i += 256) sm[F_G + i] = g_G[i];
    }
    __syncthreads();

    const int wid = threadIdx.x >> 5;
    const int lane = threadIdx.x & 31;
    const int r = lane >> 2, qq = lane & 3;
    float* stg = sm + F_SIN + wid * 256;
    float* sD  = sm + F_SD  + wid * 128;
    const uint2* btab = reinterpret_cast<const uint2*>(sm);
    const int warpGlobal = blockIdx.x * 8 + wid;

    for (int tile = warpGlobal; tile < NTILES; tile += NWARPS) {
        const int token = tile * 16 + lane;
        float x[8], cond[8];
        if (lane < 16) {
            const float4* lat4 = reinterpret_cast<const float4*>(latent);
            float4 p0 = lat4[token * 2], p1 = lat4[token * 2 + 1];
            x[0] = p0.x; x[1] = p0.y; x[2] = p0.z; x[3] = p0.w;
            x[4] = p1.x; x[5] = p1.y; x[6] = p1.z; x[7] = p1.w;
            const int cls = g_cls[(token >> 4) & (N_NODES - 1)];
            const float* sG = sm + F_G + cls * 64;
#pragma unroll
            for (int e = 0; e < 8; e++) cond[e] = 0.f;
#pragma unroll
            for (int d = 0; d < 8; d++) {
                float xd = x[d];
#pragma unroll
                for (int e = 0; e < 8; e++) cond[e] = fmaf(xd, sG[d * 8 + e], cond[e]);
            }
        }
        float logdet = 0.f;

#pragma unroll 1
        for (int blk = 0; blk < 3; blk++) {
            const int off1 = (blk & 1) ? 4 : 0;
            const int off2 = 4 - off1;
            const int tb0 = blk * 44;

            if (lane < 16) {
#pragma unroll
                for (int q = 0; q < 4; q++) stg[lane * 16 + q] = x[off1 + q];
#pragma unroll
                for (int q = 0; q < 8; q++) stg[lane * 16 + 4 + q] = cond[q];
            }
            __syncwarp();

            uint32_t Ah[4];
            {
                float2 p00 = *reinterpret_cast<float2*>(stg + r * 16 + qq * 2);
                float2 p10 = *reinterpret_cast<float2*>(stg + (r + 8) * 16 + qq * 2);
                float2 p08 = make_float2(0.f, 0.f), p18 = p08;
                if (qq < 2) {
                    p08 = *reinterpret_cast<float2*>(stg + r * 16 + qq * 2 + 8);
                    p18 = *reinterpret_cast<float2*>(stg + (r + 8) * 16 + qq * 2 + 8);
                }
                Ah[0] = h2pack(p00.x, p00.y);
                Ah[1] = h2pack(p10.x, p10.y);
                Ah[2] = h2pack(p08.x, p08.y);
                Ah[3] = h2pack(p18.x, p18.y);
            }
            __syncwarp();

            // ---- layer 0: 12(->16) -> 64 ----
            uint32_t A1h[16];
#pragma unroll
            for (int jn = 0; jn < 8; jn++) {
                float2 bia = *reinterpret_cast<const float2*>(sm + F_B0 + blk * 64 + jn * 8 + qq * 2);
                float D[4] = { bia.x, bia.y, bia.x, bia.y };
                uint2 bh = btab[(tb0 + jn) * 32 + lane];
                MMA4(D, Ah, bh.x, bh.y);
                float h0 = fmaxf(D[0], 0.f), h1 = fmaxf(D[1], 0.f);
                float h2 = fmaxf(D[2], 0.f), h3 = fmaxf(D[3], 0.f);
                A1h[jn * 2]     = h2pack(h0, h1);
                A1h[jn * 2 + 1] = h2pack(h2, h3);
            }

            // ---- layer 1: 64 -> 64 ----
            uint32_t A2h[16];
#pragma unroll
            for (int jn = 0; jn < 8; jn++) {
                float2 bia = *reinterpret_cast<const float2*>(sm + F_B1 + blk * 64 + jn * 8 + qq * 2);
                float D[4] = { bia.x, bia.y, bia.x, bia.y };
#pragma unroll
                for (int kb = 0; kb < 4; kb++) {
                    uint2 bh = btab[(tb0 + 8 + jn * 4 + kb) * 32 + lane];
                    MMA4(D, (A1h + 4 * kb), bh.x, bh.y);
                }
                float h0 = fmaxf(D[0], 0.f), h1 = fmaxf(D[1], 0.f);
                float h2 = fmaxf(D[2], 0.f), h3 = fmaxf(D[3], 0.f);
                A2h[jn * 2]     = h2pack(h0, h1);
                A2h[jn * 2 + 1] = h2pack(h2, h3);
            }

            // ---- layer 2: 64 -> 8 ----
            {
                float2 bia = *reinterpret_cast<const float2*>(sm + F_B2 + blk * 8 + qq * 2);
                float D[4] = { bia.x, bia.y, bia.x, bia.y };
#pragma unroll
                for (int kb = 0; kb < 4; kb++) {
                    uint2 bh = btab[(tb0 + 40 + kb) * 32 + lane];
                    MMA4(D, (A2h + 4 * kb), bh.x, bh.y);
                }
                sD[r * 8 + qq * 2]           = D[0];
                sD[r * 8 + qq * 2 + 1]       = D[1];
                sD[(r + 8) * 8 + qq * 2]     = D[2];
                sD[(r + 8) * 8 + qq * 2 + 1] = D[3];
            }
            __syncwarp();

            if (lane < 16) {
                float4 oa = *reinterpret_cast<float4*>(sD + lane * 8);
                float4 ob = *reinterpret_cast<float4*>(sD + lane * 8 + 4);
                float s0 = fast_tanh(oa.x), s1 = fast_tanh(oa.y);
                float s2 = fast_tanh(oa.z), s3 = fast_tanh(oa.w);
                logdet += s0 + s1 + s2 + s3;
                x[off2 + 0] = x[off2 + 0] * __expf(s0) + ob.x;
                x[off2 + 1] = x[off2 + 1] * __expf(s1) + ob.y;
                x[off2 + 2] = x[off2 + 2] * __expf(s2) + ob.z;
                x[off2 + 3] = x[off2 + 3] * __expf(s3) + ob.w;
            }
            __syncwarp();
        }

        if (lane < 16) {
            float ss = 0.f;
#pragma unroll
            for (int q = 0; q < 8; q++) ss += x[q] * x[q];
            out[token] = -0.5f * ss - 7.3515082656f + logdet;
        }
    }
}

// ============================================================================
extern "C" void kernel_launch(void* const* d_in, const int* in_sizes, int n_in,
                              void* d_out, int out_size)
{
    const float* latent = (const float*)d_in[0];
    const float* koop   = (const float*)d_in[1];
    const float* comm   = (const float*)d_in[2];
    const float* W0     = (const float*)d_in[3];
    const float* b0     = (const float*)d_in[4];
    const float* W1     = (const float*)d_in[5];
    const float* b1     = (const float*)d_in[6];
    const float* W2     = (const float*)d_in[7];
    const float* b2     = (const float*)d_in[8];
    float* out = (float*)d_out;

    eig_vals_kernel<<<C_COMM, 1>>>(koop);
    horner_kernel<<<C_COMM, 64>>>(koop);
    argmax_kernel<<<N_NODES / 256, 256>>>(comm);
    wprep_kernel<<<dim3(3, 6), 256>>>(W0, W1, W2);

    (void)cudaFuncSetAttribute(main_kernel,
                               cudaFuncAttributeMaxDynamicSharedMemorySize, SMEM_TOTAL);
    main_kernel<<<GRID_CTAS, 256, SMEM_TOTAL>>>(latent, b0, b1, b2, out);
}

// round 16
// speedup vs baseline: 2.0108x; 1.1209x over previous
#include <cuda_runtime.h>
#include <cuda_fp16.h>
#include <math.h>
#include <stdint.h>

#define N_NODES 4096
#define C_COMM  32
#define TOK     (32*4096*16)
#define NPAIRS  (TOK/32)        // 65536 warp-pairs of 32 tokens
#define GRID_CTAS 296
#define NWARPS  (GRID_CTAS*8)   // 2368

// ---------------- device scratch ----------------
__device__ float  g_G[C_COMM * 64];
__device__ int    g_cls[N_NODES];
__device__ double g_zr[C_COMM*8], g_zi[C_COMM*8], g_cr[C_COMM*8], g_ci[C_COMM*8];
// B-fragment tables: [3 blocks][44 pos][32 lanes] x uint2 (single fp16)
__device__ uint2  g_btab[3 * 44 * 32];

// ---------------- smem float layout ----------------
#define F_BTAB 0          // 8448 floats (btab as raw)
#define F_B0   8448       // 192
#define F_B1   8640       // 192
#define F_B2   8832       // 24
#define F_G    8856       // 2048
#define F_SIN  10904      // 8 warps x 32 x 16 = 4096
#define F_SD   15000      // 8 warps x 32 x 8  = 2048
#define SMEM_FLOATS 17048
#define SMEM_TOTAL  (SMEM_FLOATS*4)

// fp16 MMA: m16n8k16.f32.f16.f16.f32
#define MMA4(D, A, B0, B1) asm volatile( \
    "mma.sync.aligned.m16n8k16.row.col.f32.f16.f16.f32 " \
    "{%0,%1,%2,%3},{%4,%5,%6,%7},{%8,%9},{%0,%1,%2,%3};" \
    : "+f"((D)[0]), "+f"((D)[1]), "+f"((D)[2]), "+f"((D)[3]) \
    : "r"((A)[0]), "r"((A)[1]), "r"((A)[2]), "r"((A)[3]), "r"(B0), "r"(B1))

__device__ __forceinline__ uint32_t h2pack(float v0, float v1) {
    __half2 h = __floats2half2_rn(v0, v1);     // .x = v0 (low 16)
    return *reinterpret_cast<uint32_t*>(&h);
}

// fast transcendentals (MUFU-based)
__device__ __forceinline__ float fast_tanh(float x) {
    float e = __expf(2.f * x);
    return 1.f - __fdividef(2.f, e + 1.f);
}

// ============================================================================
// Kernel 1a: fp32 Hessenberg + Francis QR eigenvalues, fp64 Newton coeffs
// ============================================================================
__global__ void eig_vals_kernel(const float* __restrict__ koop)
{
    int c = blockIdx.x;
    if (threadIdx.x != 0) return;
    float a[8][8];
    for (int i = 0; i < 8; i++)
        for (int j = 0; j < 8; j++)
            a[i][j] = koop[c * 64 + i * 8 + j];
    for (int k = 0; k < 6; k++) {
        float nx = 0.f;
        for (int i = k + 1; i < 8; i++) nx += a[i][k] * a[i][k];
        nx = sqrtf(nx);
        if (nx < 1e-30f) continue;
        float x0 = a[k + 1][k];
        float alpha = (x0 >= 0.f) ? -nx : nx;
        float v[8];
        for (int i = 0; i < 8; i++) v[i] = 0.f;
        v[k + 1] = x0 - alpha;
        for (int i = k + 2; i < 8; i++) v[i] = a[i][k];
        float vv = 0.f;
        for (int i = k + 1; i < 8; i++) vv += v[i] * v[i];
        if (vv < 1e-30f) continue;
        float beta = 2.f / vv;
        for (int j = 0; j < 8; j++) {
            float s = 0.f;
            for (int i = k + 1; i < 8; i++) s += v[i] * a[i][j];
            s *= beta;
            for (int i = k + 1; i < 8; i++) a[i][j] -= v[i] * s;
        }
        for (int i = 0; i < 8; i++) {
            float s = 0.f;
            for (int j = k + 1; j < 8; j++) s += a[i][j] * v[j];
            s *= beta;
            for (int j = k + 1; j < 8; j++) a[i][j] -= s * v[j];
        }
    }
    float wr[8], wi[8];
    float anorm = 0.f;
    for (int i = 0; i < 8; i++) {
        int j0 = (i - 1 > 0) ? (i - 1) : 0;
        for (int j = j0; j < 8; j++) anorm += fabsf(a[i][j]);
    }
    const float EPSF = 1.1920929e-07f;
    int nn = 7; float t = 0.f; int guard = 0;
    while (nn >= 0 && guard < 2000) {
        int its = 0, l = 0;
        do {
            guard++;
            if (guard >= 2000) { wr[nn] = a[nn][nn] + t; wi[nn] = 0.f; nn--; break; }
            for (l = nn; l >= 1; l--) {
                float s = fabsf(a[l - 1][l - 1]) + fabsf(a[l][l]);
                if (s == 0.f) s = anorm;
                if (fabsf(a[l][l - 1]) <= EPSF * s) { a[l][l - 1] = 0.f; break; }
            }
            if (l < 0) l = 0;
            float x = a[nn][nn];
            if (l == nn) { wr[nn] = x + t; wi[nn] = 0.f; nn--; }
            else {
                float y = a[nn - 1][nn - 1];
                float w = a[nn][nn - 1] * a[nn - 1][nn];
                if (l == nn - 1) {
                    float p = 0.5f * (y - x);
                    float q = p * p + w;
                    float z = sqrtf(fabsf(q));
                    x += t;
                    if (q >= 0.f) {
                        z = p + ((p >= 0.f) ? z : -z);
                        wr[nn - 1] = wr[nn] = x + z;
                        if (z != 0.f) wr[nn] = x - w / z;
                        wi[nn - 1] = wi[nn] = 0.f;
                    } else {
                        wr[nn - 1] = wr[nn] = x + p;
                        wi[nn] = z; wi[nn - 1] = -z;
                    }
                    nn -= 2;
                } else {
                    float p = 0.f, q = 0.f, r = 0.f, z, s, u, v;
                    if (its == 10 || its == 20) {
                        t += x;
                        for (int i = 0; i <= nn; i++) a[i][i] -= x;
                        s = fabsf(a[nn][nn - 1]) + fabsf(a[nn - 1][nn - 2]);
                        y = x = 0.75f * s;
                        w = -0.4375f * s * s;
                    }
                    its++;
                    if (its > 50) { wr[nn] = a[nn][nn] + t; wi[nn] = 0.f; nn--; break; }
                    int m;
                    for (m = nn - 2; m >= l; m--) {
                        z = a[m][m]; r = x - z; s = y - z;
                        p = (r * s - w) / a[m + 1][m] + a[m][m + 1];
                        q = a[m + 1][m + 1] - z - r - s;
                        r = a[m + 2][m + 1];
                        s = fabsf(p) + fabsf(q) + fabsf(r);
                        p /= s; q /= s; r /= s;
                        if (m == l) break;
                        u = fabsf(a[m][m - 1]) * (fabsf(q) + fabsf(r));
                        v = fabsf(p) * (fabsf(a[m - 1][m - 1]) + fabsf(z) + fabsf(a[m + 1][m + 1]));
                        if (u <= EPSF * v) break;
                    }
                    for (int i = m + 2; i <= nn; i++) {
                        a[i][i - 2] = 0.f;
                        if (i != m + 2) a[i][i - 3] = 0.f;
                    }
                    for (int k = m; k <= nn - 1; k++) {
                        if (k != m) {
                            p = a[k][k - 1]; q = a[k + 1][k - 1];
                            r = (k != nn - 1) ? a[k + 2][k - 1] : 0.f;
                            x = fabsf(p) + fabsf(q) + fabsf(r);
                            if (x != 0.f) { p /= x; q /= x; r /= x; }
                        }
                        s = sqrtf(p * p + q * q + r * r);
                        if (p < 0.f) s = -s;
                        if (s != 0.f) {
                            if (k == m) { if (l != m) a[k][k - 1] = -a[k][k - 1]; }
                            else a[k][k - 1] = -s * x;
                            p += s; x = p / s; y = q / s; z = r / s; q /= p; r /= p;
                            for (int j = k; j <= nn; j++) {
                                float pp = a[k][j] + q * a[k + 1][j];
                                if (k != nn - 1) { pp += r * a[k + 2][j]; a[k + 2][j] -= pp * z; }
                                a[k + 1][j] -= pp * y;
                                a[k][j]     -= pp * x;
                            }
                            int mmin = (nn < k + 3) ? nn : (k + 3);
                            for (int i = l; i <= mmin; i++) {
                                float pp = x * a[i][k] + y * a[i][k + 1];
                                if (k != nn - 1) { pp += z * a[i][k + 2]; a[i][k + 2] -= pp * r; }
                                a[i][k + 1] -= pp * q;
                                a[i][k]     -= pp;
                            }
                        }
                    }
                }
            }
        } while (l < nn - 1);
    }
    double zr[8], zi[8];
    for (int i = 0; i < 8; i++) { zr[i] = (double)wr[i] + 1e-10; zi[i] = (double)wi[i] + 1e-10; }
    bool mask[8]; bool any = false;
    for (int i = 0; i < 8; i++) {
        double am = sqrt(zr[i] * zr[i] + zi[i] * zi[i]);
        mask[i] = (am <= 1.1 && am >= 0.9);
        any = any || mask[i];
    }
    if (!any) for (int i = 0; i < 8; i++) mask[i] = true;
    for (int i = 1; i < 8; i++)
        for (int j = 0; j < i; j++)
            if (fabs(zr[i] - zr[j]) < 1e-9 && fabs(zi[i] - zi[j]) < 1e-9) {
                zr[i] += 1.0e-8 * (i + 1);
                zi[i] += 0.7e-8 * (i + 1);
            }
    double cr[8], ci[8];
    for (int i = 0; i < 8; i++) {
        cr[i] = mask[i] ? zr[i] : 0.0;
        ci[i] = mask[i] ? zi[i] : 0.0;
    }
    for (int j = 1; j < 8; j++)
        for (int i = 7; i >= j; i--) {
            double nr = cr[i] - cr[i - 1], ni = ci[i] - ci[i - 1];
            double dr = zr[i] - zr[i - j], di = zi[i] - zi[i - j];
            double d2 = dr * dr + di * di;
            cr[i] = (nr * dr + ni * di) / d2;
            ci[i] = (ni * dr - nr * di) / d2;
        }
    for (int i = 0; i < 8; i++) {
        g_zr[c * 8 + i] = zr[i]; g_zi[c * 8 + i] = zi[i];
        g_cr[c * 8 + i] = cr[i]; g_ci[c * 8 + i] = ci[i];
    }
}

// ============================================================================
// Kernel 1b: parallel complex Horner p(A) -> G (64 threads per matrix, fp64)
// ============================================================================
__global__ void horner_kernel(const float* __restrict__ koop)
{
    int c = blockIdx.x;
    int t = threadIdx.x;
    int i = t >> 3, j = t & 7;
    __shared__ double sA[64], sMr[64], sMi[64], szr[8], szi[8], scr[8], sci[8];
    sA[t] = (double)koop[c * 64 + t];
    if (t < 8) {
        szr[t] = g_zr[c * 8 + t]; szi[t] = g_zi[c * 8 + t];
        scr[t] = g_cr[c * 8 + t]; sci[t] = g_ci[c * 8 + t];
    }
    __syncthreads();
    double mr = (i == j) ? scr[7] : 0.0;
    double mi = (i == j) ? sci[7] : 0.0;
    sMr[t] = mr; sMi[t] = mi;
    __syncthreads();
    for (int k = 6; k >= 0; k--) {
        double tr = 0.0, ti = 0.0;
#pragma unroll
        for (int q = 0; q < 8; q++) {
            tr += sA[i * 8 + q] * sMr[q * 8 + j];
            ti += sA[i * 8 + q] * sMi[q * 8 + j];
        }
        double omr = mr, omi = mi;
        __syncthreads();
        mr = tr - (szr[k] * omr - szi[k] * omi) + ((i == j) ? scr[k] : 0.0);
        mi = ti - (szr[k] * omi + szi[k] * omr) + ((i == j) ? sci[k] : 0.0);
        sMr[t] = mr; sMi[t] = mi;
        __syncthreads();
    }
    g_G[c * 64 + t] = (float)mr;
}

// ============================================================================
// Kernel 2: community argmax
// ============================================================================
__global__ void argmax_kernel(const float* __restrict__ comm)
{
    int n = blockIdx.x * blockDim.x + threadIdx.x;
    if (n >= N_NODES) return;
    float best = comm[n * C_COMM];
    int bi = 0;
#pragma unroll
    for (int cc = 1; cc < C_COMM; cc++) {
        float v = comm[n * C_COMM + cc];
        if (v > best) { best = v; bi = cc; }
    }
    g_cls[n] = bi;
}

// ============================================================================
// Kernel 3: build per-lane B-fragment tables (single fp16, m16n8k16 layout).
// grid = (3 blocks, 6 slabs). pos map per block (44 pos):
// L0: jn (8) | L1: 8 + jn*4+kb (32) | L2: 40 + kb (4).
// ============================================================================
__global__ void wprep_kernel(const float* __restrict__ W0,
                             const float* __restrict__ W1,
                             const float* __restrict__ W2)
{
    int blk = blockIdx.x;
    int idx = blockIdx.y * 256 + threadIdx.x;
    if (idx >= 44 * 32) return;
    {
        int pos = idx >> 5, lane = idx & 31;
        int jn, kb, layer;
        if (pos < 8)       { layer = 0; jn = pos; kb = 0; }
        else if (pos < 40) { int p = pos - 8; kb = p & 3; jn = p >> 2; layer = 1; }
        else               { layer = 2; kb = pos - 40; jn = 0; }
        int n = jn * 8 + (lane >> 2);
        int k0 = 16 * kb + 2 * (lane & 3);
        __half w[4];
#pragma unroll
        for (int e = 0; e < 4; e++) {
            int k = k0 + (e >> 1) * 8 + (e & 1);
            float val = 0.f;
            if (layer == 0)      { if (k < 12) val = W0[blk * 768 + k * 64 + n]; }
            else if (layer == 1) { val = W1[blk * 4096 + k * 64 + n]; }
            else                 { val = W2[blk * 512 + k * 8 + n]; }
            w[e] = __float2half_rn(val);
        }
        uint32_t px = ((uint32_t)__half_as_ushort(w[1]) << 16)
                    |  (uint32_t)__half_as_ushort(w[0]);
        uint32_t py = ((uint32_t)__half_as_ushort(w[3]) << 16)
                    |  (uint32_t)__half_as_ushort(w[2]);
        g_btab[(blk * 44 + pos) * 32 + lane] = make_uint2(px, py);
    }
}

// ============================================================================
// Kernel 4: main fused flow via fp16 mma.sync. Persistent; warp = 32 tokens
// (two m16 tiles T0/T1 sharing every B-fragment load; all lanes own a token).
// ============================================================================
__global__ void __launch_bounds__(256, 2) main_kernel(
    const float* __restrict__ latent,
    const float* __restrict__ b0g, const float* __restrict__ b1g,
    const float* __restrict__ b2g, float* __restrict__ out)
{
    extern __shared__ float sm[];
    {
        const uint4* src = reinterpret_cast<const uint4*>(g_btab);
        uint4* dst = reinterpret_cast<uint4*>(sm);
        for (int i = threadIdx.x; i < 8448 / 4; i += 256) dst[i] = src[i];
        for (int i = threadIdx.x; i < 192;  i += 256) sm[F_B0 + i] = b0g[i];
        for (int i = threadIdx.x; i < 192;  i += 256) sm[F_B1 + i] = b1g[i];
        for (int i = threadIdx.x; i < 24;   i += 256) sm[F_B2 + i] = b2g[i];
        for (int i = threadIdx.x; i < 2048; i += 256) sm[F_G + i] = g_G[i];
    }
    __syncthreads();

    const int wid = threadIdx.x >> 5;
    const int lane = threadIdx.x & 31;
    const int r = lane >> 2, qq = lane & 3;
    float* stg = sm + F_SIN + wid * 512;    // [32 tok][16]
    float* sD  = sm + F_SD  + wid * 256;    // [32 tok][8]
    const uint2* btab = reinterpret_cast<const uint2*>(sm);
    const int warpGlobal = blockIdx.x * 8 + wid;

    for (int pair = warpGlobal; pair < NPAIRS; pair += NWARPS) {
        const int token = pair * 32 + lane;       // every lane owns one token
        float x[8], cond[8];
        {
            const float4* lat4 = reinterpret_cast<const float4*>(latent);
            float4 p0 = lat4[token * 2], p1 = lat4[token * 2 + 1];
            x[0] = p0.x; x[1] = p0.y; x[2] = p0.z; x[3] = p0.w;
            x[4] = p1.x; x[5] = p1.y; x[6] = p1.z; x[7] = p1.w;
            const int cls = g_cls[(token >> 4) & (N_NODES - 1)];
            const float* sG = sm + F_G + cls * 64;
#pragma unroll
            for (int e = 0; e < 8; e++) cond[e] = 0.f;
#pragma unroll
            for (int d = 0; d < 8; d++) {
                float xd = x[d];
#pragma unroll
                for (int e = 0; e < 8; e++) cond[e] = fmaf(xd, sG[d * 8 + e], cond[e]);
            }
        }
        float logdet = 0.f;

#pragma unroll 1
        for (int blk = 0; blk < 3; blk++) {
            const int off1 = (blk & 1) ? 4 : 0;
            const int off2 = 4 - off1;
            const int tb0 = blk * 44;

            // stage in12 for all 32 tokens
#pragma unroll
            for (int q = 0; q < 4; q++) stg[lane * 16 + q] = x[off1 + q];
#pragma unroll
            for (int q = 0; q < 8; q++) stg[lane * 16 + 4 + q] = cond[q];
            __syncwarp();

            // A fragments: T0 = rows 0..15, T1 = rows 16..31
            uint32_t A0h[4], A1hf[4];
            {
                float2 a00 = *reinterpret_cast<float2*>(stg + r * 16 + qq * 2);
                float2 a10 = *reinterpret_cast<float2*>(stg + (r + 8) * 16 + qq * 2);
                float2 b00 = *reinterpret_cast<float2*>(stg + (16 + r) * 16 + qq * 2);
                float2 b10 = *reinterpret_cast<float2*>(stg + (24 + r) * 16 + qq * 2);
                float2 a08 = make_float2(0.f, 0.f), a18 = a08, b08 = a08, b18 = a08;
                if (qq < 2) {
                    a08 = *reinterpret_cast<float2*>(stg + r * 16 + qq * 2 + 8);
                    a18 = *reinterpret_cast<float2*>(stg + (r + 8) * 16 + qq * 2 + 8);
                    b08 = *reinterpret_cast<float2*>(stg + (16 + r) * 16 + qq * 2 + 8);
                    b18 = *reinterpret_cast<float2*>(stg + (24 + r) * 16 + qq * 2 + 8);
                }
                A0h[0] = h2pack(a00.x, a00.y);
                A0h[1] = h2pack(a10.x, a10.y);
                A0h[2] = h2pack(a08.x, a08.y);
                A0h[3] = h2pack(a18.x, a18.y);
                A1hf[0] = h2pack(b00.x, b00.y);
                A1hf[1] = h2pack(b10.x, b10.y);
                A1hf[2] = h2pack(b08.x, b08.y);
                A1hf[3] = h2pack(b18.x, b18.y);
            }
            __syncwarp();

            // ---- layer 0: 12(->16) -> 64 ----
            uint32_t H10[16], H11[16];
#pragma unroll
            for (int jn = 0; jn < 8; jn++) {
                float2 bia = *reinterpret_cast<const float2*>(sm + F_B0 + blk * 64 + jn * 8 + qq * 2);
                float D0[4] = { bia.x, bia.y, bia.x, bia.y };
                float D1[4] = { bia.x, bia.y, bia.x, bia.y };
                uint2 bh = btab[(tb0 + jn) * 32 + lane];
                MMA4(D0, A0h, bh.x, bh.y);
                MMA4(D1, A1hf, bh.x, bh.y);
                H10[jn * 2]     = h2pack(fmaxf(D0[0], 0.f), fmaxf(D0[1], 0.f));
                H10[jn * 2 + 1] = h2pack(fmaxf(D0[2], 0.f), fmaxf(D0[3], 0.f));
                H11[jn * 2]     = h2pack(fmaxf(D1[0], 0.f), fmaxf(D1[1], 0.f));
                H11[jn * 2 + 1] = h2pack(fmaxf(D1[2], 0.f), fmaxf(D1[3], 0.f));
            }

            // ---- layer 1: 64 -> 64 ----
            uint32_t H20[16], H21[16];
#pragma unroll
            for (int jn = 0; jn < 8; jn++) {
                float2 bia = *reinterpret_cast<const float2*>(sm + F_B1 + blk * 64 + jn * 8 + qq * 2);
                float D0[4] = { bia.x, bia.y, bia.x, bia.y };
                float D1[4] = { bia.x, bia.y, bia.x, bia.y };
#pragma unroll
                for (int kb = 0; kb < 4; kb++) {
                    uint2 bh = btab[(tb0 + 8 + jn * 4 + kb) * 32 + lane];
                    MMA4(D0, (H10 + 4 * kb), bh.x, bh.y);
                    MMA4(D1, (H11 + 4 * kb), bh.x, bh.y);
                }
                H20[jn * 2]     = h2pack(fmaxf(D0[0], 0.f), fmaxf(D0[1], 0.f));
                H20[jn * 2 + 1] = h2pack(fmaxf(D0[2], 0.f), fmaxf(D0[3], 0.f));
                H21[jn * 2]     = h2pack(fmaxf(D1[0], 0.f), fmaxf(D1[1], 0.f));
                H21[jn * 2 + 1] = h2pack(fmaxf(D1[2], 0.f), fmaxf(D1[3], 0.f));
            }

            // ---- layer 2: 64 -> 8 ----
            {
                float2 bia = *reinterpret_cast<const float2*>(sm + F_B2 + blk * 8 + qq * 2);
                float D0[4] = { bia.x, bia.y, bia.x, bia.y };
                float D1[4] = { bia.x, bia.y, bia.x, bia.y };
#pragma unroll
                for (int kb = 0; kb < 4; kb++) {
                    uint2 bh = btab[(tb0 + 40 + kb) * 32 + lane];
                    MMA4(D0, (H20 + 4 * kb), bh.x, bh.y);
                    MMA4(D1, (H21 + 4 * kb), bh.x, bh.y);
                }
                sD[r * 8 + qq * 2]              = D0[0];
                sD[r * 8 + qq * 2 + 1]          = D0[1];
                sD[(r + 8) * 8 + qq * 2]        = D0[2];
                sD[(r + 8) * 8 + qq * 2 + 1]    = D0[3];
                sD[(16 + r) * 8 + qq * 2]       = D1[0];
                sD[(16 + r) * 8 + qq * 2 + 1]   = D1[1];
                sD[(24 + r) * 8 + qq * 2]       = D1[2];
                sD[(24 + r) * 8 + qq * 2 + 1]   = D1[3];
            }
            __syncwarp();

            // coupling update: every lane handles its own token
            {
                float4 oa = *reinterpret_cast<float4*>(sD + lane * 8);
                float4 ob = *reinterpret_cast<float4*>(sD + lane * 8 + 4);
                float s0 = fast_tanh(oa.x), s1 = fast_tanh(oa.y);
                float s2 = fast_tanh(oa.z), s3 = fast_tanh(oa.w);
                logdet += s0 + s1 + s2 + s3;
                x[off2 + 0] = x[off2 + 0] * __expf(s0) + ob.x;
                x[off2 + 1] = x[off2 + 1] * __expf(s1) + ob.y;
                x[off2 + 2] = x[off2 + 2] * __expf(s2) + ob.z;
                x[off2 + 3] = x[off2 + 3] * __expf(s3) + ob.w;
            }
            __syncwarp();
        }

        {
            float ss = 0.f;
#pragma unroll
            for (int q = 0; q < 8; q++) ss += x[q] * x[q];
            out[token] = -0.5f * ss - 7.3515082656f + logdet;
        }
    }
}

// ============================================================================
extern "C" void kernel_launch(void* const* d_in, const int* in_sizes, int n_in,
                              void* d_out, int out_size)
{
    const float* latent = (const float*)d_in[0];
    const float* koop   = (const float*)d_in[1];
    const float* comm   = (const float*)d_in[2];
    const float* W0     = (const float*)d_in[3];
    const float* b0     = (const float*)d_in[4];
    const float* W1     = (const float*)d_in[5];
    const float* b1     = (const float*)d_in[6];
    const float* W2     = (const float*)d_in[7];
    const float* b2     = (const float*)d_in[8];
    float* out = (float*)d_out;

    eig_vals_kernel<<<C_COMM, 1>>>(koop);
    horner_kernel<<<C_COMM, 64>>>(koop);
    argmax_kernel<<<N_NODES / 256, 256>>>(comm);
    wprep_kernel<<<dim3(3, 6), 256>>>(W0, W1, W2);

    (void)cudaFuncSetAttribute(main_kernel,
                               cudaFuncAttributeMaxDynamicSharedMemorySize, SMEM_TOTAL);
    main_kernel<<<GRID_CTAS, 256, SMEM_TOTAL>>>(latent, b0, b1, b2, out);
}

// round 17
// speedup vs baseline: 2.2425x; 1.1152x over previous
#include <cuda_runtime.h>
#include <cuda_fp16.h>
#include <math.h>
#include <stdint.h>

#define N_NODES 4096
#define C_COMM  32
#define TOK     (32*4096*16)
#define NPAIRS  (TOK/32)        // 65536 warp-pairs of 32 tokens
#define GRID_CTAS 296
#define NWARPS  (GRID_CTAS*8)   // 2368

// ---------------- device scratch ----------------
__device__ float  g_G[C_COMM * 64];
__device__ int    g_cls[N_NODES];
__device__ double g_zr[C_COMM*8], g_zi[C_COMM*8], g_cr[C_COMM*8], g_ci[C_COMM*8];
// B-fragment tables: [3 blocks][44 pos][32 lanes] x uint2 (single fp16)
__device__ uint2  g_btab[3 * 44 * 32];

// ---------------- smem float layout (main kernel) ----------------
#define F_BTAB 0          // 8448 floats (btab as raw)
#define F_B0   8448       // 192
#define F_B1   8640       // 192
#define F_B2   8832       // 24
#define F_G    8856       // 2048
#define F_SIN  10904      // 8 warps x 32 x 16 = 4096
#define F_SD   15000      // 8 warps x 32 x 8  = 2048
#define SMEM_FLOATS 17048
#define SMEM_TOTAL  (SMEM_FLOATS*4)

// fp16 MMA: m16n8k16.f32.f16.f16.f32
#define MMA4(D, A, B0, B1) asm volatile( \
    "mma.sync.aligned.m16n8k16.row.col.f32.f16.f16.f32 " \
    "{%0,%1,%2,%3},{%4,%5,%6,%7},{%8,%9},{%0,%1,%2,%3};" \
    : "+f"((D)[0]), "+f"((D)[1]), "+f"((D)[2]), "+f"((D)[3]) \
    : "r"((A)[0]), "r"((A)[1]), "r"((A)[2]), "r"((A)[3]), "r"(B0), "r"(B1))

__device__ __forceinline__ uint32_t h2pack(float v0, float v1) {
    __half2 h = __floats2half2_rn(v0, v1);     // .x = v0 (low 16)
    return *reinterpret_cast<uint32_t*>(&h);
}

// fast transcendentals (MUFU-based)
__device__ __forceinline__ float fast_tanh(float x) {
    float e = __expf(2.f * x);
    return 1.f - __fdividef(2.f, e + 1.f);
}

// ============================================================================
// Kernel 1a: warp-parallel fp32 Hessenberg + Francis QR (1 warp per matrix,
// a[8][8] in shared; inner row/col update loops distributed across lanes —
// bit-identical arithmetic to the serial version). fp64 Newton tail on lane 0.
// ============================================================================
__global__ void eig_vals_kernel(const float* __restrict__ koop)
{
    const int c = blockIdx.x;
    const int t = threadIdx.x;          // 32 lanes
    __shared__ float a[64];
    __shared__ float v[8];
#define A_(i, j) a[(i) * 8 + (j)]
    a[t] = koop[c * 64 + t];
    a[t + 32] = koop[c * 64 + t + 32];
    __syncwarp();

    // ---- Householder -> Hessenberg ----
    for (int k = 0; k < 6; k++) {
        float nx = 0.f;
        for (int i = k + 1; i < 8; i++) nx += A_(i, k) * A_(i, k);
        nx = sqrtf(nx);
        if (nx < 1e-30f) continue;
        float x0 = A_(k + 1, k);
        float alpha = (x0 >= 0.f) ? -nx : nx;
        if (t < 8) {
            float vt = 0.f;
            if (t == k + 1) vt = x0 - alpha;
            else if (t >= k + 2) vt = A_(t, k);
            v[t] = vt;
        }
        __syncwarp();
        float vv = 0.f;
        for (int i = k + 1; i < 8; i++) vv += v[i] * v[i];
        if (vv < 1e-30f) continue;
        float beta = 2.f / vv;
        if (t < 8) {                    // column update: lane t owns column t
            float s = 0.f;
            for (int i = k + 1; i < 8; i++) s += v[i] * A_(i, t);
            s *= beta;
            for (int i = k + 1; i < 8; i++) A_(i, t) -= v[i] * s;
        }
        __syncwarp();
        if (t < 8) {                    // row update: lane t owns row t
            float s = 0.f;
            for (int j = k + 1; j < 8; j++) s += A_(t, j) * v[j];
            s *= beta;
            for (int j = k + 1; j < 8; j++) A_(t, j) -= s * v[j];
        }
        __syncwarp();
    }

    // ---- Francis double-shift QR (uniform control flow, distributed updates)
    float wr[8], wi[8];
    float anorm = 0.f;
    for (int i = 0; i < 8; i++) {
        int j0 = (i - 1 > 0) ? (i - 1) : 0;
        for (int j = j0; j < 8; j++) anorm += fabsf(A_(i, j));
    }
    const float EPSF = 1.1920929e-07f;
    int nn = 7; float tsh = 0.f; int guard = 0;
    while (nn >= 0 && guard < 2000) {
        int its = 0, l = 0;
        do {
            guard++;
            if (guard >= 2000) { wr[nn] = A_(nn, nn) + tsh; wi[nn] = 0.f; nn--; break; }
            for (l = nn; l >= 1; l--) {
                float s = fabsf(A_(l - 1, l - 1)) + fabsf(A_(l, l));
                if (s == 0.f) s = anorm;
                if (fabsf(A_(l, l - 1)) <= EPSF * s) { A_(l, l - 1) = 0.f; break; }
            }
            if (l < 0) l = 0;
            float x = A_(nn, nn);
            if (l == nn) { wr[nn] = x + tsh; wi[nn] = 0.f; nn--; }
            else {
                float y = A_(nn - 1, nn - 1);
                float w = A_(nn, nn - 1) * A_(nn - 1, nn);
                if (l == nn - 1) {
                    float p = 0.5f * (y - x);
                    float q = p * p + w;
                    float z = sqrtf(fabsf(q));
                    x += tsh;
                    if (q >= 0.f) {
                        z = p + ((p >= 0.f) ? z : -z);
                        wr[nn - 1] = wr[nn] = x + z;
                        if (z != 0.f) wr[nn] = x - w / z;
                        wi[nn - 1] = wi[nn] = 0.f;
                    } else {
                        wr[nn - 1] = wr[nn] = x + p;
                        wi[nn] = z; wi[nn - 1] = -z;
                    }
                    nn -= 2;
                } else {
                    float p = 0.f, q = 0.f, r = 0.f, z, s, u, vq;
                    if (its == 10 || its == 20) {
                        tsh += x;
                        __syncwarp();
                        if (t <= nn) A_(t, t) -= x;     // distributed RMW
                        __syncwarp();
                        s = fabsf(A_(nn, nn - 1)) + fabsf(A_(nn - 1, nn - 2));
                        y = x = 0.75f * s;
                        w = -0.4375f * s * s;
                    }
                    its++;
                    if (its > 50) { wr[nn] = A_(nn, nn) + tsh; wi[nn] = 0.f; nn--; break; }
                    int m;
                    for (m = nn - 2; m >= l; m--) {
                        z = A_(m, m); r = x - z; s = y - z;
                        p = (r * s - w) / A_(m + 1, m) + A_(m, m + 1);
                        q = A_(m + 1, m + 1) - z - r - s;
                        r = A_(m + 2, m + 1);
                        s = fabsf(p) + fabsf(q) + fabsf(r);
                        p /= s; q /= s; r /= s;
                        if (m == l) break;
                        u = fabsf(A_(m, m - 1)) * (fabsf(q) + fabsf(r));
                        vq = fabsf(p) * (fabsf(A_(m - 1, m - 1)) + fabsf(z) + fabsf(A_(m + 1, m + 1)));
                        if (u <= EPSF * vq) break;
                    }
                    __syncwarp();
                    if (t >= m + 2 && t <= nn) {        // distributed constant zeroing
                        A_(t, t - 2) = 0.f;
                        if (t != m + 2) A_(t, t - 3) = 0.f;
                    }
                    __syncwarp();
                    for (int k = m; k <= nn - 1; k++) {
                        // phase A: redundant scalar reads
                        if (k != m) {
                            p = A_(k, k - 1); q = A_(k + 1, k - 1);
                            r = (k != nn - 1) ? A_(k + 2, k - 1) : 0.f;
                            x = fabsf(p) + fabsf(q) + fabsf(r);
                            if (x != 0.f) { p /= x; q /= x; r /= x; }
                        }
                        s = sqrtf(p * p + q * q + r * r);
                        if (p < 0.f) s = -s;
                        float akk1_new = 0.f; int wr_akk1 = 0;
                        if (s != 0.f) {
                            if (k == m) {
                                if (l != m) { akk1_new = -A_(k, k - 1); wr_akk1 = 1; }
                            } else { akk1_new = -s * x; wr_akk1 = 1; }
                            p += s; x = p / s; y = q / s; z = r / s; q /= p; r /= p;
                        }
                        __syncwarp();   // all reads done before any write
                        if (s != 0.f) {
                            if (t == 0 && wr_akk1) A_(k, k - 1) = akk1_new;
                            int j = k + t;              // distributed column update
                            if (j <= nn) {
                                float pp = A_(k, j) + q * A_(k + 1, j);
                                if (k != nn - 1) { pp += r * A_(k + 2, j); A_(k + 2, j) -= pp * z; }
                                A_(k + 1, j) -= pp * y;
                                A_(k, j)     -= pp * x;
                            }
                        }
                        __syncwarp();
                        if (s != 0.f) {
                            int mmin = (nn < k + 3) ? nn : (k + 3);
                            int i = l + t;              // distributed row update
                            if (i <= mmin) {
                                float pp = x * A_(i, k) + y * A_(i, k + 1);
                                if (k != nn - 1) { pp += z * A_(i, k + 2); A_(i, k + 2) -= pp * r; }
                                A_(i, k + 1) -= pp * q;
                                A_(i, k)     -= pp;
                            }
                        }
                        __syncwarp();
                    }
                }
            }
        } while (l < nn - 1);
    }

    // ---- fp64 Newton tail (lane 0 only; identical arithmetic) ----
    if (t == 0) {
        double zr[8], zi[8];
        for (int i = 0; i < 8; i++) { zr[i] = (double)wr[i] + 1e-10; zi[i] = (double)wi[i] + 1e-10; }
        bool mask[8]; bool any = false;
        for (int i = 0; i < 8; i++) {
            double am = sqrt(zr[i] * zr[i] + zi[i] * zi[i]);
            mask[i] = (am <= 1.1 && am >= 0.9);
            any = any || mask[i];
        }
        if (!any) for (int i = 0; i < 8; i++) mask[i] = true;
        for (int i = 1; i < 8; i++)
            for (int j = 0; j < i; j++)
                if (fabs(zr[i] - zr[j]) < 1e-9 && fabs(zi[i] - zi[j]) < 1e-9) {
                    zr[i] += 1.0e-8 * (i + 1);
                    zi[i] += 0.7e-8 * (i + 1);
                }
        double cr[8], ci[8];
        for (int i = 0; i < 8; i++) {
            cr[i] = mask[i] ? zr[i] : 0.0;
            ci[i] = mask[i] ? zi[i] : 0.0;
        }
        for (int j = 1; j < 8; j++)
            for (int i = 7; i >= j; i--) {
                double nr = cr[i] - cr[i - 1], ni = ci[i] - ci[i - 1];
                double dr = zr[i] - zr[i - j], di = zi[i] - zi[i - j];
                double d2 = dr * dr + di * di;
                cr[i] = (nr * dr + ni * di) / d2;
                ci[i] = (ni * dr - nr * di) / d2;
            }
        for (int i = 0; i < 8; i++) {
            g_zr[c * 8 + i] = zr[i]; g_zi[c * 8 + i] = zi[i];
            g_cr[c * 8 + i] = cr[i]; g_ci[c * 8 + i] = ci[i];
        }
    }
#undef A_
}

// ============================================================================
// Kernel 1b: parallel complex Horner p(A) -> G (64 threads per matrix, fp64)
// ============================================================================
__global__ void horner_kernel(const float* __restrict__ koop)
{
    int c = blockIdx.x;
    int t = threadIdx.x;
    int i = t >> 3, j = t & 7;
    __shared__ double sA[64], sMr[64], sMi[64], szr[8], szi[8], scr[8], sci[8];
    sA[t] = (double)koop[c * 64 + t];
    if (t < 8) {
        szr[t] = g_zr[c * 8 + t]; szi[t] = g_zi[c * 8 + t];
        scr[t] = g_cr[c * 8 + t]; sci[t] = g_ci[c * 8 + t];
    }
    __syncthreads();
    double mr = (i == j) ? scr[7] : 0.0;
    double mi = (i == j) ? sci[7] : 0.0;
    sMr[t] = mr; sMi[t] = mi;
    __syncthreads();
    for (int k = 6; k >= 0; k--) {
        double tr = 0.0, ti = 0.0;
#pragma unroll
        for (int q = 0; q < 8; q++) {
            tr += sA[i * 8 + q] * sMr[q * 8 + j];
            ti += sA[i * 8 + q] * sMi[q * 8 + j];
        }
        double omr = mr, omi = mi;
        __syncthreads();
        mr = tr - (szr[k] * omr - szi[k] * omi) + ((i == j) ? scr[k] : 0.0);
        mi = ti - (szr[k] * omi + szi[k] * omr) + ((i == j) ? sci[k] : 0.0);
        sMr[t] = mr; sMi[t] = mi;
        __syncthreads();
    }
    g_G[c * 64 + t] = (float)mr;
}

// ============================================================================
// Kernel 2: community argmax
// ============================================================================
__global__ void argmax_kernel(const float* __restrict__ comm)
{
    int n = blockIdx.x * blockDim.x + threadIdx.x;
    if (n >= N_NODES) return;
    float best = comm[n * C_COMM];
    int bi = 0;
#pragma unroll
    for (int cc = 1; cc < C_COMM; cc++) {
        float v = comm[n * C_COMM + cc];
        if (v > best) { best = v; bi = cc; }
    }
    g_cls[n] = bi;
}

// ============================================================================
// Kernel 3: build per-lane B-fragment tables (single fp16, m16n8k16 layout).
// grid = (3 blocks, 6 slabs). pos map per block (44 pos):
// L0: jn (8) | L1: 8 + jn*4+kb (32) | L2: 40 + kb (4).
// ============================================================================
__global__ void wprep_kernel(const float* __restrict__ W0,
                             const float* __restrict__ W1,
                             const float* __restrict__ W2)
{
    int blk = blockIdx.x;
    int idx = blockIdx.y * 256 + threadIdx.x;
    if (idx >= 44 * 32) return;
    {
        int pos = idx >> 5, lane = idx & 31;
        int jn, kb, layer;
        if (pos < 8)       { layer = 0; jn = pos; kb = 0; }
        else if (pos < 40) { int p = pos - 8; kb = p & 3; jn = p >> 2; layer = 1; }
        else               { layer = 2; kb = pos - 40; jn = 0; }
        int n = jn * 8 + (lane >> 2);
        int k0 = 16 * kb + 2 * (lane & 3);
        __half w[4];
#pragma unroll
        for (int e = 0; e < 4; e++) {
            int k = k0 + (e >> 1) * 8 + (e & 1);
            float val = 0.f;
            if (layer == 0)      { if (k < 12) val = W0[blk * 768 + k * 64 + n]; }
            else if (layer == 1) { val = W1[blk * 4096 + k * 64 + n]; }
            else                 { val = W2[blk * 512 + k * 8 + n]; }
            w[e] = __float2half_rn(val);
        }
        uint32_t px = ((uint32_t)__half_as_ushort(w[1]) << 16)
                    |  (uint32_t)__half_as_ushort(w[0]);
        uint32_t py = ((uint32_t)__half_as_ushort(w[3]) << 16)
                    |  (uint32_t)__half_as_ushort(w[2]);
        g_btab[(blk * 44 + pos) * 32 + lane] = make_uint2(px, py);
    }
}

// ============================================================================
// Kernel 4: main fused flow via fp16 mma.sync. Persistent; warp = 32 tokens
// (two m16 tiles T0/T1 sharing every B-fragment load; all lanes own a token).
// UNCHANGED from R16 winner — protected.
// ============================================================================
__global__ void __launch_bounds__(256, 2) main_kernel(
    const float* __restrict__ latent,
    const float* __restrict__ b0g, const float* __restrict__ b1g,
    const float* __restrict__ b2g, float* __restrict__ out)
{
    extern __shared__ float sm[];
    {
        const uint4* src = reinterpret_cast<const uint4*>(g_btab);
        uint4* dst = reinterpret_cast<uint4*>(sm);
        for (int i = threadIdx.x; i < 8448 / 4; i += 256) dst[i] = src[i];
        for (int i = threadIdx.x; i < 192;  i += 256) sm[F_B0 + i] = b0g[i];
        for (int i = threadIdx.x; i < 192;  i += 256) sm[F_B1 + i] = b1g[i];
        for (int i = threadIdx.x; i < 24;   i += 256) sm[F_B2 + i] = b2g[i];
        for (int i = threadIdx.x; i < 2048; i += 256) sm[F_G + i] = g_G[i];
    }
    __syncthreads();

    const int wid = threadIdx.x >> 5;
    const int lane = threadIdx.x & 31;
    const int r = lane >> 2, qq = lane & 3;
    float* stg = sm + F_SIN + wid * 512;    // [32 tok][16]
    float* sD  = sm + F_SD  + wid * 256;    // [32 tok][8]
    const uint2* btab = reinterpret_cast<const uint2*>(sm);
    const int warpGlobal = blockIdx.x * 8 + wid;

    for (int pair = warpGlobal; pair < NPAIRS; pair += NWARPS) {
        const int token = pair * 32 + lane;       // every lane owns one token
        float x[8], cond[8];
        {
            const float4* lat4 = reinterpret_cast<const float4*>(latent);
            float4 p0 = lat4[token * 2], p1 = lat4[token * 2 + 1];
            x[0] = p0.x; x[1] = p0.y; x[2] = p0.z; x[3] = p0.w;
            x[4] = p1.x; x[5] = p1.y; x[6] = p1.z; x[7] = p1.w;
            const int cls = g_cls[(token >> 4) & (N_NODES - 1)];
            const float* sG = sm + F_G + cls * 64;
#pragma unroll
            for (int e = 0; e < 8; e++) cond[e] = 0.f;
#pragma unroll
            for (int d = 0; d < 8; d++) {
                float xd = x[d];
#pragma unroll
                for (int e = 0; e < 8; e++) cond[e] = fmaf(xd, sG[d * 8 + e], cond[e]);
            }
        }
        float logdet = 0.f;

#pragma unroll 1
        for (int blk = 0; blk < 3; blk++) {
            const int off1 = (blk & 1) ? 4 : 0;
            const int off2 = 4 - off1;
            const int tb0 = blk * 44;

            // stage in12 for all 32 tokens
#pragma unroll
            for (int q = 0; q < 4; q++) stg[lane * 16 + q] = x[off1 + q];
#pragma unroll
            for (int q = 0; q < 8; q++) stg[lane * 16 + 4 + q] = cond[q];
            __syncwarp();

            // A fragments: T0 = rows 0..15, T1 = rows 16..31
            uint32_t A0h[4], A1hf[4];
            {
                float2 a00 = *reinterpret_cast<float2*>(stg + r * 16 + qq * 2);
                float2 a10 = *reinterpret_cast<float2*>(stg + (r + 8) * 16 + qq * 2);
                float2 b00 = *reinterpret_cast<float2*>(stg + (16 + r) * 16 + qq * 2);
                float2 b10 = *reinterpret_cast<float2*>(stg + (24 + r) * 16 + qq * 2);
                float2 a08 = make_float2(0.f, 0.f), a18 = a08, b08 = a08, b18 = a08;
                if (qq < 2) {
                    a08 = *reinterpret_cast<float2*>(stg + r * 16 + qq * 2 + 8);
                    a18 = *reinterpret_cast<float2*>(stg + (r + 8) * 16 + qq * 2 + 8);
                    b08 = *reinterpret_cast<float2*>(stg + (16 + r) * 16 + qq * 2 + 8);
                    b18 = *reinterpret_cast<float2*>(stg + (24 + r) * 16 + qq * 2 + 8);
                }
                A0h[0] = h2pack(a00.x, a00.y);
                A0h[1] = h2pack(a10.x, a10.y);
                A0h[2] = h2pack(a08.x, a08.y);
                A0h[3] = h2pack(a18.x, a18.y);
                A1hf[0] = h2pack(b00.x, b00.y);
                A1hf[1] = h2pack(b10.x, b10.y);
                A1hf[2] = h2pack(b08.x, b08.y);
                A1hf[3] = h2pack(b18.x, b18.y);
            }
            __syncwarp();

            // ---- layer 0: 12(->16) -> 64 ----
            uint32_t H10[16], H11[16];
#pragma unroll
            for (int jn = 0; jn < 8; jn++) {
                float2 bia = *reinterpret_cast<const float2*>(sm + F_B0 + blk * 64 + jn * 8 + qq * 2);
                float D0[4] = { bia.x, bia.y, bia.x, bia.y };
                float D1[4] = { bia.x, bia.y, bia.x, bia.y };
                uint2 bh = btab[(tb0 + jn) * 32 + lane];
                MMA4(D0, A0h, bh.x, bh.y);
                MMA4(D1, A1hf, bh.x, bh.y);
                H10[jn * 2]     = h2pack(fmaxf(D0[0], 0.f), fmaxf(D0[1], 0.f));
                H10[jn * 2 + 1] = h2pack(fmaxf(D0[2], 0.f), fmaxf(D0[3], 0.f));
                H11[jn * 2]     = h2pack(fmaxf(D1[0], 0.f), fmaxf(D1[1], 0.f));
                H11[jn * 2 + 1] = h2pack(fmaxf(D1[2], 0.f), fmaxf(D1[3], 0.f));
            }

            // ---- layer 1: 64 -> 64 ----
            uint32_t H20[16], H21[16];
#pragma unroll
            for (int jn = 0; jn < 8; jn++) {
                float2 bia = *reinterpret_cast<const float2*>(sm + F_B1 + blk * 64 + jn * 8 + qq * 2);
                float D0[4] = { bia.x, bia.y, bia.x, bia.y };
                float D1[4] = { bia.x, bia.y, bia.x, bia.y };
#pragma unroll
                for (int kb = 0; kb < 4; kb++) {
                    uint2 bh = btab[(tb0 + 8 + jn * 4 + kb) * 32 + lane];
                    MMA4(D0, (H10 + 4 * kb), bh.x, bh.y);
                    MMA4(D1, (H11 + 4 * kb), bh.x, bh.y);
                }
                H20[jn * 2]     = h2pack(fmaxf(D0[0], 0.f), fmaxf(D0[1], 0.f));
                H20[jn * 2 + 1] = h2pack(fmaxf(D0[2], 0.f), fmaxf(D0[3], 0.f));
                H21[jn * 2]     = h2pack(fmaxf(D1[0], 0.f), fmaxf(D1[1], 0.f));
                H21[jn * 2 + 1] = h2pack(fmaxf(D1[2], 0.f), fmaxf(D1[3], 0.f));
            }

            // ---- layer 2: 64 -> 8 ----
            {
                float2 bia = *reinterpret_cast<const float2*>(sm + F_B2 + blk * 8 + qq * 2);
                float D0[4] = { bia.x, bia.y, bia.x, bia.y };
                float D1[4] = { bia.x, bia.y, bia.x, bia.y };
#pragma unroll
                for (int kb = 0; kb < 4; kb++) {
                    uint2 bh = btab[(tb0 + 40 + kb) * 32 + lane];
                    MMA4(D0, (H20 + 4 * kb), bh.x, bh.y);
                    MMA4(D1, (H21 + 4 * kb), bh.x, bh.y);
                }
                sD[r * 8 + qq * 2]              = D0[0];
                sD[r * 8 + qq * 2 + 1]          = D0[1];
                sD[(r + 8) * 8 + qq * 2]        = D0[2];
                sD[(r + 8) * 8 + qq * 2 + 1]    = D0[3];
                sD[(16 + r) * 8 + qq * 2]       = D1[0];
                sD[(16 + r) * 8 + qq * 2 + 1]   = D1[1];
                sD[(24 + r) * 8 + qq * 2]       = D1[2];
                sD[(24 + r) * 8 + qq * 2 + 1]   = D1[3];
            }
            __syncwarp();

            // coupling update: every lane handles its own token
            {
                float4 oa = *reinterpret_cast<float4*>(sD + lane * 8);
                float4 ob = *reinterpret_cast<float4*>(sD + lane * 8 + 4);
                float s0 = fast_tanh(oa.x), s1 = fast_tanh(oa.y);
                float s2 = fast_tanh(oa.z), s3 = fast_tanh(oa.w);
                logdet += s0 + s1 + s2 + s3;
                x[off2 + 0] = x[off2 + 0] * __expf(s0) + ob.x;
                x[off2 + 1] = x[off2 + 1] * __expf(s1) + ob.y;
                x[off2 + 2] = x[off2 + 2] * __expf(s2) + ob.z;
                x[off2 + 3] = x[off2 + 3] * __expf(s3) + ob.w;
            }
            __syncwarp();
        }

        {
            float ss = 0.f;
#pragma unroll
            for (int q = 0; q < 8; q++) ss += x[q] * x[q];
            out[token] = -0.5f * ss - 7.3515082656f + logdet;
        }
    }
}

// ============================================================================
extern "C" void kernel_launch(void* const* d_in, const int* in_sizes, int n_in,
                              void* d_out, int out_size)
{
    const float* latent = (const float*)d_in[0];
    const float* koop   = (const float*)d_in[1];
    const float* comm   = (const float*)d_in[2];
    const float* W0     = (const float*)d_in[3];
    const float* b0     = (const float*)d_in[4];
    const float* W1     = (const float*)d_in[5];
    const float* b1     = (const float*)d_in[6];
    const float* W2     = (const float*)d_in[7];
    const float* b2     = (const float*)d_in[8];
    float* out = (float*)d_out;

    eig_vals_kernel<<<C_COMM, 32>>>(koop);
    horner_kernel<<<C_COMM, 64>>>(koop);
    argmax_kernel<<<N_NODES / 256, 256>>>(comm);
    wprep_kernel<<<dim3(3, 6), 256>>>(W0, W1, W2);

    (void)cudaFuncSetAttribute(main_kernel,
                               cudaFuncAttributeMaxDynamicSharedMemorySize, SMEM_TOTAL);
    main_kernel<<<GRID_CTAS, 256, SMEM_TOTAL>>>(latent, b0, b1, b2, out);
}